// round 15
// baseline (speedup 1.0000x reference)
#include <cuda_runtime.h>
#include <cuda_bf16.h>
#include <math.h>
#include <stdint.h>

// ---------------- problem constants ----------------
#define BB 2
#define SQ 1024
#define D_ 2048
#define HN 16
#define HD 128
#define NTOK (BB*SQ)       // 2048
#define EE 8
#define DE_ 704
#define NSLOT (NTOK*2)     // 4096 (top-2 per token)

typedef __nv_bfloat16 bf16;

// ---------------- scratch (device globals: no allocations allowed) ----------------
__device__ float g_q   [NTOK*D_];
__device__ float g_k   [NTOK*D_];
__device__ float g_v   [NTOK*D_];
__device__ float g_h   [NTOK*D_];
__device__ float g_xn2 [NTOK*D_];
__device__ float g_gb  [NSLOT*DE_];
__device__ float g_ub  [NSLOT*DE_];
__device__ float g_op  [NSLOT*D_];
__device__ int   g_cnt [EE];
__device__ int   g_cur [EE];
__device__ int   g_off [EE];
__device__ int   g_tope[NTOK*2];
__device__ float g_topw[NTOK*2];
__device__ int   g_slot_tok[NSLOT];
__device__ float g_slot_w  [NSLOT];
__device__ int   g_tok_pos [NTOK*2];
// bf16 hi/lo activation planes
__device__ bf16 g_xnh[NTOK*D_],  g_xnl[NTOK*D_];
__device__ bf16 g_qh [NTOK*D_],  g_ql [NTOK*D_];
__device__ bf16 g_kh [NTOK*D_],  g_kl [NTOK*D_];
__device__ bf16 g_vth[NTOK*D_],  g_vtl[NTOK*D_];    // V transposed [bh][HD][SQ]
__device__ bf16 g_ah [NTOK*D_],  g_al [NTOK*D_];    // attention out planes
__device__ bf16 g_x2h[NTOK*D_],  g_x2l[NTOK*D_];
__device__ bf16 g_ih [NSLOT*DE_], g_il [NSLOT*DE_];
// bf16 hi/lo weight planes (split once per call)
__device__ bf16 g_wqh[D_*D_], g_wql[D_*D_];
__device__ bf16 g_wkh[D_*D_], g_wkl[D_*D_];
__device__ bf16 g_wvh[D_*D_], g_wvl[D_*D_];
__device__ bf16 g_woh[D_*D_], g_wol[D_*D_];
__device__ bf16 g_egh[EE*DE_*D_], g_egl[EE*DE_*D_];
__device__ bf16 g_euh[EE*DE_*D_], g_eul[EE*DE_*D_];
__device__ bf16 g_edh[EE*D_*DE_], g_edl[EE*D_*DE_];

// ---------------- helpers ----------------
__device__ __forceinline__ uint32_t smem_u32(const void* p) {
    uint32_t a;
    asm("{ .reg .u64 t; cvta.to.shared.u64 t, %1; cvt.u32.u64 %0, t; }" : "=r"(a) : "l"(p));
    return a;
}
__device__ __forceinline__ void mma_bf16(float* c, const uint32_t* a,
                                         uint32_t b0, uint32_t b1) {
    asm volatile(
        "mma.sync.aligned.m16n8k16.row.col.f32.bf16.bf16.f32 "
        "{%0,%1,%2,%3}, {%4,%5,%6,%7}, {%8,%9}, {%0,%1,%2,%3};"
        : "+f"(c[0]), "+f"(c[1]), "+f"(c[2]), "+f"(c[3])
        : "r"(a[0]), "r"(a[1]), "r"(a[2]), "r"(a[3]), "r"(b0), "r"(b1));
}
__device__ __forceinline__ void ldsm4(uint32_t& r0, uint32_t& r1, uint32_t& r2,
                                      uint32_t& r3, uint32_t addr) {
    asm volatile("ldmatrix.sync.aligned.m8n8.x4.shared.b16 {%0,%1,%2,%3}, [%4];"
                 : "=r"(r0), "=r"(r1), "=r"(r2), "=r"(r3) : "r"(addr));
}
__device__ __forceinline__ void split2(float x0, float x1, uint32_t& wh, uint32_t& wl) {
    bf16 h0 = __float2bfloat16(x0);
    bf16 h1 = __float2bfloat16(x1);
    bf16 l0 = __float2bfloat16(x0 - __bfloat162float(h0));
    bf16 l1 = __float2bfloat16(x1 - __bfloat162float(h1));
    wh = ((uint32_t)__bfloat16_as_ushort(h1) << 16) | __bfloat16_as_ushort(h0);
    wl = ((uint32_t)__bfloat16_as_ushort(l1) << 16) | __bfloat16_as_ushort(l0);
}
__device__ __forceinline__ void split1(float x, bf16& h, bf16& l) {
    h = __float2bfloat16(x);
    l = __float2bfloat16(x - __bfloat162float(h));
}
__device__ __forceinline__ void cpa16(uint32_t dst, const void* src) {
    asm volatile("cp.async.ca.shared.global [%0], [%1], 16;" :: "r"(dst), "l"(src));
}
__device__ __forceinline__ void cpa16z(uint32_t dst, const void* src, int sz) {
    asm volatile("cp.async.ca.shared.global [%0], [%1], 16, %2;"
                 :: "r"(dst), "l"(src), "r"(sz));
}
#define CP_COMMIT() asm volatile("cp.async.commit_group;" ::: "memory")
#define CP_WAIT0()  asm volatile("cp.async.wait_group 0;" ::: "memory")
#define CP_WAIT1()  asm volatile("cp.async.wait_group 1;" ::: "memory")

// ---------------- bf16-plane tensor GEMM (cp.async 2-stage + ldmatrix) ----------
// C[M,N] = A[M,K] * W[N,K]^T (+add). A/W are bf16 hi/lo planes.
// MODE 0: dense. MODE 1: A rows gathered via g_slot_tok. MODE 2: A rows contiguous.
// FUSE 1: QKV (blockIdx.x/16 selects W/C). FUSE 2: gate+up (x>=6 -> W2/C2).
#define TM 128
#define TN 128
#define BK 16
#define PL 6144          // bytes per plane per stage (128 rows x 48B)
#define STG 24576        // bytes per stage (4 planes)

template<int MODE, int FUSE = 0>
__global__ void __launch_bounds__(256) gemm_bfp(
    const bf16* __restrict__ AH, const bf16* __restrict__ AL,
    const bf16* __restrict__ WH, const bf16* __restrict__ WL,
    float* __restrict__ C, const float* __restrict__ addp,
    int M, int Nn, int Kk, long wstride,
    const bf16* __restrict__ W2H, const bf16* __restrict__ W2L, float* __restrict__ C2,
    const bf16* __restrict__ W3H, const bf16* __restrict__ W3L, float* __restrict__ C3)
{
    __shared__ __align__(16) uint8_t sm[2 * STG];   // 48KB static -> 2 CTA/SM
    uint32_t sb = smem_u32(sm);

    int e = blockIdx.z;
    int Mloc = M, base = 0;
    int bx = blockIdx.x;
    const bf16* WbH = WH; const bf16* WbL = WL;
    float* Cp = C;
    if (FUSE == 1) {
        int sel = bx >> 4; bx &= 15;
        WbH = (sel == 0) ? WH : ((sel == 1) ? W2H : W3H);
        WbL = (sel == 0) ? WL : ((sel == 1) ? W2L : W3L);
        Cp  = (sel == 0) ? C  : ((sel == 1) ? C2  : C3);
    }
    if (FUSE == 2) {
        if (bx >= 6) { bx -= 6; WbH = W2H; WbL = W2L; Cp = C2; }
    }
    const bf16* WpH = WbH; const bf16* WpL = WbL;
    if (MODE != 0) {
        Mloc = g_cnt[e]; base = g_off[e];
        WpH = WbH + (size_t)e * (size_t)wstride;
        WpL = WbL + (size_t)e * (size_t)wstride;
    }
    int m0 = blockIdx.y * TM;
    if (m0 >= Mloc) return;
    int n0 = bx * TN;
    int tid = threadIdx.x;

    // staging: thread -> (row = tid>>1, 16B chunk = tid&1); 6 cp.async per stage
    int srow = tid >> 1, ch = tid & 1;
    uint32_t dOff = (uint32_t)(srow * 48 + ch * 16);
    int gm = m0 + srow;
    bool av = gm < Mloc;
    int arow;
    if (MODE == 0)      arow = av ? gm : 0;
    else if (MODE == 1) arow = av ? g_slot_tok[base + gm] : 0;
    else                arow = av ? (base + gm) : 0;
    const bf16* pAh = AH + (size_t)arow * Kk + ch * 8;
    const bf16* pAl = AL + (size_t)arow * Kk + ch * 8;
    int asz = av ? 16 : 0;
    int gn = n0 + srow;
    bool bv = gn < Nn;
    const bf16* pBh = WpH + (size_t)(bv ? gn : 0) * Kk + ch * 8;
    const bf16* pBl = WpL + (size_t)(bv ? gn : 0) * Kk + ch * 8;
    int bsz = bv ? 16 : 0;

    int lane = tid & 31, g = lane >> 2, tg = lane & 3;
    int wm = (tid >> 5) & 3;
    int wn = tid >> 7;
    int mbase = wm * 32, nbase = wn * 64;

    uint32_t aoff[2], boff[4];
#pragma unroll
    for (int mt = 0; mt < 2; mt++)
        aoff[mt] = (uint32_t)((mbase + mt * 16 + (lane & 7) + ((lane >> 3) & 1) * 8) * 48
                              + ((lane >> 4) & 1) * 16);
#pragma unroll
    for (int p = 0; p < 4; p++)
        boff[p] = (uint32_t)((nbase + p * 16 + (lane & 7) + ((lane >> 4) & 1) * 8) * 48
                             + ((lane >> 3) & 1) * 16);

    float acc[2][8][4];
#pragma unroll
    for (int mt = 0; mt < 2; mt++)
#pragma unroll
        for (int nt = 0; nt < 8; nt++)
#pragma unroll
            for (int q = 0; q < 4; q++) acc[mt][nt][q] = 0.f;

    int nk = Kk / BK;

    // prologue: fill both stages
#pragma unroll
    for (int s = 0; s < 2; s++) {
        if (s < nk) {
            uint32_t st = sb + s * STG;
            int k0 = s * BK;
            cpa16z(st + dOff,          pAh + k0, asz);
            cpa16z(st + PL + dOff,     pAl + k0, asz);
            cpa16z(st + 2*PL + dOff,   pBh + k0, bsz);
            cpa16z(st + 3*PL + dOff,   pBl + k0, bsz);
        }
        CP_COMMIT();
    }

    int buf = 0;
    for (int it = 0; it < nk; it++) {
        CP_WAIT1();
        __syncthreads();

        uint32_t st = sb + (uint32_t)buf * STG;
        uint32_t ah[2][4], al[2][4];
#pragma unroll
        for (int mt = 0; mt < 2; mt++) {
            ldsm4(ah[mt][0], ah[mt][1], ah[mt][2], ah[mt][3], st + aoff[mt]);
            ldsm4(al[mt][0], al[mt][1], al[mt][2], al[mt][3], st + PL + aoff[mt]);
        }
#pragma unroll
        for (int p = 0; p < 4; p++) {
            uint32_t b00, b01, b10, b11, c00, c01, c10, c11;
            ldsm4(b00, b01, b10, b11, st + 2*PL + boff[p]);
            ldsm4(c00, c01, c10, c11, st + 3*PL + boff[p]);
#pragma unroll
            for (int mt = 0; mt < 2; mt++) {
                mma_bf16(acc[mt][2*p],   ah[mt], b00, b01);
                mma_bf16(acc[mt][2*p],   ah[mt], c00, c01);
                mma_bf16(acc[mt][2*p],   al[mt], b00, b01);
                mma_bf16(acc[mt][2*p+1], ah[mt], b10, b11);
                mma_bf16(acc[mt][2*p+1], ah[mt], c10, c11);
                mma_bf16(acc[mt][2*p+1], al[mt], b10, b11);
            }
        }
        __syncthreads();   // all warps done reading this stage

        if (it + 2 < nk) {
            int k0 = (it + 2) * BK;
            cpa16z(st + dOff,          pAh + k0, asz);
            cpa16z(st + PL + dOff,     pAl + k0, asz);
            cpa16z(st + 2*PL + dOff,   pBh + k0, bsz);
            cpa16z(st + 3*PL + dOff,   pBl + k0, bsz);
        }
        CP_COMMIT();
        buf ^= 1;
    }

    // epilogue: c0/c1 -> (row g, cols 2tg,2tg+1), c2/c3 -> row g+8
#pragma unroll
    for (int mt = 0; mt < 2; mt++) {
#pragma unroll
        for (int nt = 0; nt < 8; nt++) {
            int gc = n0 + nbase + nt * 8 + tg * 2;
            if (gc >= Nn) continue;
            int gm0 = m0 + mbase + mt * 16 + g;
#pragma unroll
            for (int hrow = 0; hrow < 2; hrow++) {
                int gmr = gm0 + hrow * 8;
                if (gmr >= Mloc) continue;
                int crow = (MODE == 0) ? gmr : (base + gmr);
                size_t off = (size_t)crow * Nn + gc;
                float2 vv = make_float2(acc[mt][nt][hrow * 2], acc[mt][nt][hrow * 2 + 1]);
                if (MODE == 0 && addp) {
                    float2 rv = *(const float2*)(addp + off);
                    vv.x += rv.x; vv.y += rv.y;
                }
                *(float2*)(Cp + off) = vv;
            }
        }
    }
}

// ---------------- weight split: fp32 -> bf16 hi/lo planes ----------------
__global__ void splitw_k(const float* __restrict__ src, bf16* __restrict__ h,
                         bf16* __restrict__ l, int n4) {
    for (int i = blockIdx.x * 256 + threadIdx.x; i < n4; i += gridDim.x * 256) {
        float4 v = *(const float4*)(src + i * 4);
        uint32_t h0, l0, h1, l1;
        split2(v.x, v.y, h0, l0);
        split2(v.z, v.w, h1, l1);
        *(uint32_t*)(h + i * 4)     = h0;
        *(uint32_t*)(h + i * 4 + 2) = h1;
        *(uint32_t*)(l + i * 4)     = l0;
        *(uint32_t*)(l + i * 4 + 2) = l1;
    }
}

// ---------------- RMSNorm with split output ----------------
__global__ void rmsnorm_sp_k(const float* __restrict__ x, const float* __restrict__ w,
                             float* __restrict__ o, bf16* __restrict__ oh,
                             bf16* __restrict__ ol) {
    int n = blockIdx.x;
    const float* xr = x + (size_t)n * D_;
    float s = 0.f;
    for (int d = threadIdx.x; d < D_; d += 256) { float v = xr[d]; s += v * v; }
    __shared__ float red[256];
    red[threadIdx.x] = s; __syncthreads();
    for (int st = 128; st > 0; st >>= 1) {
        if (threadIdx.x < st) red[threadIdx.x] += red[threadIdx.x + st];
        __syncthreads();
    }
    float inv = rsqrtf(red[0] / (float)D_ + 1e-6f);
    size_t ro = (size_t)n * D_;
    for (int d = threadIdx.x; d < D_; d += 256) {
        float v = xr[d] * inv * w[d];
        if (o) o[ro + d] = v;
        bf16 h, l;
        split1(v, h, l);
        oh[ro + d] = h; ol[ro + d] = l;
    }
}

// ---------------- fused RoPE + bf16 hi/lo split for Q,K ----------------
__global__ void rope_split_k(const int* __restrict__ pos) {
    int idx = blockIdx.x * 256 + threadIdx.x;
    if (idx >= NTOK * HN * 64) return;
    int j  = idx & 63;
    int hh = (idx >> 6) & 15;
    int t  = idx >> 10;
    float p = (float)pos[t];
    float inv = expf(-((float)(2 * j) / 128.0f) * 9.210340371976184f);
    float fr = p * inv;
    float sn, cs;
    sincosf(fr, &sn, &cs);
    size_t base = (size_t)t * D_ + hh * HD + j;
    bf16 h, l;
    float x1 = g_q[base], x2 = g_q[base + 64];
    float r1 = x1 * cs - x2 * sn, r2 = x2 * cs + x1 * sn;
    split1(r1, h, l); g_qh[base] = h;      g_ql[base] = l;
    split1(r2, h, l); g_qh[base + 64] = h; g_ql[base + 64] = l;
    x1 = g_k[base]; x2 = g_k[base + 64];
    r1 = x1 * cs - x2 * sn; r2 = x2 * cs + x1 * sn;
    split1(r1, h, l); g_kh[base] = h;      g_kl[base] = l;
    split1(r2, h, l); g_kh[base + 64] = h; g_kl[base + 64] = l;
}

// ---------------- split V + transpose to [bh][dim][seq] bf16 hi/lo ----------------
__global__ void splitv_k() {
    __shared__ bf16 sh[32][33], sl[32][33];
    int tx = threadIdx.x, ty = threadIdx.y;      // (32, 8)
    int s0 = blockIdx.x * 32;
    int d0 = blockIdx.y * 32;
    int bh = blockIdx.z;
    int b = bh >> 4, hh = bh & 15;
#pragma unroll
    for (int i = 0; i < 4; i++) {
        int sr = ty + i * 8;
        float v = g_v[((size_t)(b * SQ + s0 + sr)) * D_ + hh * HD + d0 + tx];
        bf16 h, l;
        split1(v, h, l);
        sh[sr][tx] = h; sl[sr][tx] = l;
    }
    __syncthreads();
#pragma unroll
    for (int i = 0; i < 4; i++) {
        int dr = ty + i * 8;
        size_t o = ((size_t)bh * HD + d0 + dr) * SQ + s0 + tx;
        g_vth[o] = sh[tx][dr];
        g_vtl[o] = sl[tx][dr];
    }
}

// ---------------- flash attention: smem-staged K/V + mma.sync bf16x3 ----------------
// grid (SQ/64, HN, BB), block 128. Epilogue writes bf16 hi/lo planes for O-proj.
__global__ void __launch_bounds__(128) attn_mma_k()
{
    __shared__ __align__(16) uint8_t sm[49152];
    uint32_t sb = smem_u32(sm);
    int tid = threadIdx.x;
    int w = tid >> 5, lane = tid & 31;
    int g = lane >> 2, tg = lane & 3;
    int hh = blockIdx.y, b = blockIdx.z;
    int qsb = blockIdx.x * 64;
    int qs0 = qsb + w * 16;
    int bh = b * HN + hh;

    uint32_t qfh[8][4], qfl[8][4];
    size_t qr0 = ((size_t)(b * SQ + qs0 + g)) * D_ + hh * HD;
    size_t qr1 = qr0 + (size_t)8 * D_;
#pragma unroll
    for (int ks = 0; ks < 8; ks++) {
        int c0 = ks * 16 + 2 * tg;
        qfh[ks][0] = *(const uint32_t*)&g_qh[qr0 + c0];
        qfh[ks][1] = *(const uint32_t*)&g_qh[qr1 + c0];
        qfh[ks][2] = *(const uint32_t*)&g_qh[qr0 + c0 + 8];
        qfh[ks][3] = *(const uint32_t*)&g_qh[qr1 + c0 + 8];
        qfl[ks][0] = *(const uint32_t*)&g_ql[qr0 + c0];
        qfl[ks][1] = *(const uint32_t*)&g_ql[qr1 + c0];
        qfl[ks][2] = *(const uint32_t*)&g_ql[qr0 + c0 + 8];
        qfl[ks][3] = *(const uint32_t*)&g_ql[qr1 + c0 + 8];
    }

    uint32_t lm_row = (lane & 7) + ((lane >> 4) & 1) * 8;
    uint32_t lm_col = ((lane >> 3) & 1) * 16;

    float m0 = -1e30f, m1 = -1e30f, l0 = 0.f, l1 = 0.f;
    float Oa[16][4];
#pragma unroll
    for (int nt = 0; nt < 16; nt++)
#pragma unroll
        for (int q = 0; q < 4; q++) Oa[nt][q] = 0.f;

    const float SC = 0.08838834764831845f;
    int row0 = qs0 + g, row1 = row0 + 8;
    int nsteps = qsb / 32 + 2;

    for (int step = 0; step < nsteps; step++) {
        int kt = step * 32;
        {
            size_t kg = ((size_t)(b * SQ + kt)) * D_ + hh * HD;
#pragma unroll
            for (int i = 0; i < 4; i++) {
                int idx = tid * 4 + i;
                int tok = idx >> 4, ks = (idx >> 1) & 7, c = idx & 1;
                size_t so = kg + (size_t)tok * D_ + ks * 16 + c * 8;
                uint32_t dst = sb + (uint32_t)(ks * 1536 + tok * 48 + c * 16);
                cpa16(dst,         g_kh + so);
                cpa16(dst + 12288, g_kl + so);
            }
            size_t vg = (size_t)bh * HD * SQ + kt;
#pragma unroll
            for (int i = 0; i < 4; i++) {
                int idx = tid * 4 + i;
                int dim = idx >> 2, ks2 = (idx >> 1) & 1, c = idx & 1;
                size_t so = vg + (size_t)dim * SQ + ks2 * 16 + c * 8;
                uint32_t dst = sb + 24576u + (uint32_t)(ks2 * 6144 + dim * 48 + c * 16);
                cpa16(dst,         g_vth + so);
                cpa16(dst + 12288, g_vtl + so);
            }
        }
        CP_COMMIT();
        CP_WAIT0();
        __syncthreads();

        float s[4][4];
#pragma unroll
        for (int nt = 0; nt < 4; nt++)
#pragma unroll
            for (int q = 0; q < 4; q++) s[nt][q] = 0.f;

#pragma unroll
        for (int ks = 0; ks < 8; ks++) {
#pragma unroll
            for (int p = 0; p < 2; p++) {
                uint32_t ka = sb + (uint32_t)(ks * 1536 + (p * 16 + lm_row) * 48) + lm_col;
                uint32_t b00, b01, b10, b11, c00, c01, c10, c11;
                ldsm4(b00, b01, b10, b11, ka);
                ldsm4(c00, c01, c10, c11, ka + 12288);
                mma_bf16(s[2*p],   qfh[ks], b00, b01);
                mma_bf16(s[2*p],   qfh[ks], c00, c01);
                mma_bf16(s[2*p],   qfl[ks], b00, b01);
                mma_bf16(s[2*p+1], qfh[ks], b10, b11);
                mma_bf16(s[2*p+1], qfh[ks], c10, c11);
                mma_bf16(s[2*p+1], qfl[ks], b10, b11);
            }
        }

#pragma unroll
        for (int nt = 0; nt < 4; nt++) {
            int col = kt + nt * 8 + 2 * tg;
            s[nt][0] = (col     <= row0) ? s[nt][0] * SC : -1e30f;
            s[nt][1] = (col + 1 <= row0) ? s[nt][1] * SC : -1e30f;
            s[nt][2] = (col     <= row1) ? s[nt][2] * SC : -1e30f;
            s[nt][3] = (col + 1 <= row1) ? s[nt][3] * SC : -1e30f;
        }

        float mx0 = -1e30f, mx1 = -1e30f;
#pragma unroll
        for (int nt = 0; nt < 4; nt++) {
            mx0 = fmaxf(mx0, fmaxf(s[nt][0], s[nt][1]));
            mx1 = fmaxf(mx1, fmaxf(s[nt][2], s[nt][3]));
        }
        mx0 = fmaxf(mx0, __shfl_xor_sync(0xffffffff, mx0, 1));
        mx0 = fmaxf(mx0, __shfl_xor_sync(0xffffffff, mx0, 2));
        mx1 = fmaxf(mx1, __shfl_xor_sync(0xffffffff, mx1, 1));
        mx1 = fmaxf(mx1, __shfl_xor_sync(0xffffffff, mx1, 2));
        float mn0 = fmaxf(m0, mx0), mn1 = fmaxf(m1, mx1);
        float a0 = __expf(m0 - mn0), a1 = __expf(m1 - mn1);
        float sum0 = 0.f, sum1 = 0.f;
#pragma unroll
        for (int nt = 0; nt < 4; nt++) {
            s[nt][0] = __expf(s[nt][0] - mn0);
            s[nt][1] = __expf(s[nt][1] - mn0);
            s[nt][2] = __expf(s[nt][2] - mn1);
            s[nt][3] = __expf(s[nt][3] - mn1);
            sum0 += s[nt][0] + s[nt][1];
            sum1 += s[nt][2] + s[nt][3];
        }
        sum0 += __shfl_xor_sync(0xffffffff, sum0, 1);
        sum0 += __shfl_xor_sync(0xffffffff, sum0, 2);
        sum1 += __shfl_xor_sync(0xffffffff, sum1, 1);
        sum1 += __shfl_xor_sync(0xffffffff, sum1, 2);
        l0 = l0 * a0 + sum0; l1 = l1 * a1 + sum1;
        m0 = mn0; m1 = mn1;

#pragma unroll
        for (int nt = 0; nt < 16; nt++) {
            Oa[nt][0] *= a0; Oa[nt][1] *= a0;
            Oa[nt][2] *= a1; Oa[nt][3] *= a1;
        }

        uint32_t pah[2][4], pal[2][4];
#pragma unroll
        for (int ks2 = 0; ks2 < 2; ks2++) {
            int na = ks2 * 2, nb = na + 1;
            split2(s[na][0], s[na][1], pah[ks2][0], pal[ks2][0]);
            split2(s[na][2], s[na][3], pah[ks2][1], pal[ks2][1]);
            split2(s[nb][0], s[nb][1], pah[ks2][2], pal[ks2][2]);
            split2(s[nb][2], s[nb][3], pah[ks2][3], pal[ks2][3]);
        }

#pragma unroll
        for (int ks2 = 0; ks2 < 2; ks2++) {
#pragma unroll
            for (int p = 0; p < 8; p++) {
                uint32_t va = sb + 24576u
                            + (uint32_t)(ks2 * 6144 + (p * 16 + lm_row) * 48) + lm_col;
                uint32_t v00, v01, v10, v11, u00, u01, u10, u11;
                ldsm4(v00, v01, v10, v11, va);
                ldsm4(u00, u01, u10, u11, va + 12288);
                mma_bf16(Oa[2*p],   pah[ks2], v00, v01);
                mma_bf16(Oa[2*p],   pah[ks2], u00, u01);
                mma_bf16(Oa[2*p],   pal[ks2], v00, v01);
                mma_bf16(Oa[2*p+1], pah[ks2], v10, v11);
                mma_bf16(Oa[2*p+1], pah[ks2], u10, u11);
                mma_bf16(Oa[2*p+1], pal[ks2], v10, v11);
            }
        }
        __syncthreads();
    }

    // epilogue: write bf16 hi/lo planes
    float i0 = 1.f / l0, i1 = 1.f / l1;
    size_t or0 = ((size_t)(b * SQ + qs0 + g)) * D_ + hh * HD;
    size_t or1 = or0 + (size_t)8 * D_;
#pragma unroll
    for (int nt = 0; nt < 16; nt++) {
        int col = nt * 8 + 2 * tg;
        uint32_t h, l;
        split2(Oa[nt][0] * i0, Oa[nt][1] * i0, h, l);
        *(uint32_t*)&g_ah[or0 + col] = h;
        *(uint32_t*)&g_al[or0 + col] = l;
        split2(Oa[nt][2] * i1, Oa[nt][3] * i1, h, l);
        *(uint32_t*)&g_ah[or1 + col] = h;
        *(uint32_t*)&g_al[or1 + col] = l;
    }
}

// ---------------- MoE routing ----------------
__global__ void zero_k() {
    if (threadIdx.x < EE) { g_cnt[threadIdx.x] = 0; g_cur[threadIdx.x] = 0; }
}

__global__ void route1_k(const float* __restrict__ x, const float* __restrict__ gw) {
    int n = blockIdx.x;
    float part[EE];
#pragma unroll
    for (int e = 0; e < EE; e++) part[e] = 0.f;
    for (int d = threadIdx.x; d < D_; d += 256) {
        float xv = x[(size_t)n * D_ + d];
#pragma unroll
        for (int e = 0; e < EE; e++) part[e] = fmaf(xv, gw[e * D_ + d], part[e]);
    }
    __shared__ float red[256];
    __shared__ float lg[EE];
    for (int e = 0; e < EE; e++) {
        red[threadIdx.x] = part[e]; __syncthreads();
        for (int st = 128; st > 0; st >>= 1) {
            if (threadIdx.x < st) red[threadIdx.x] += red[threadIdx.x + st];
            __syncthreads();
        }
        if (threadIdx.x == 0) lg[e] = red[0];
        __syncthreads();
    }
    if (threadIdx.x == 0) {
        int i0 = 0; float b0 = lg[0];
        for (int e = 1; e < EE; e++) if (lg[e] > b0) { b0 = lg[e]; i0 = e; }
        int i1 = -1; float b1 = -1e30f;
        for (int e = 0; e < EE; e++) { if (e == i0) continue; if (lg[e] > b1) { b1 = lg[e]; i1 = e; } }
        float m = fmaxf(b0, b1);
        float w0 = __expf(b0 - m), w1 = __expf(b1 - m);
        float s = w0 + w1; w0 /= s; w1 /= s;
        g_tope[n*2] = i0; g_tope[n*2+1] = i1;
        g_topw[n*2] = w0; g_topw[n*2+1] = w1;
        atomicAdd(&g_cnt[i0], 1); atomicAdd(&g_cnt[i1], 1);
    }
}

__global__ void scan_k() {
    int o = 0;
    for (int e = 0; e < EE; e++) { g_off[e] = o; o += g_cnt[e]; }
}

__global__ void assign_k() {
    int n = blockIdx.x * 256 + threadIdx.x;
    if (n >= NTOK) return;
#pragma unroll
    for (int kk = 0; kk < 2; kk++) {
        int e = g_tope[n*2 + kk];
        int p = g_off[e] + atomicAdd(&g_cur[e], 1);
        g_slot_tok[p] = n;
        g_slot_w[p]   = g_topw[n*2 + kk];
        g_tok_pos[n*2 + kk] = p;
    }
}

// ---------------- swiglu with split output ----------------
__global__ void swiglu_k() {
    int i = blockIdx.x * 256 + threadIdx.x;
    if (i >= NSLOT * DE_) return;
    float g = g_gb[i], u = g_ub[i];
    float sig = 1.f / (1.f + __expf(-g));
    float v = g * sig * u;
    bf16 h, l;
    split1(v, h, l);
    g_ih[i] = h; g_il[i] = l;
}

__global__ void final_k(float* __restrict__ out) {
    int n = blockIdx.x;
    int p0 = g_tok_pos[n*2], p1 = g_tok_pos[n*2 + 1];
    float w0 = g_slot_w[p0], w1 = g_slot_w[p1];
    size_t hb = (size_t)n * D_;
    for (int d = threadIdx.x * 4; d < D_; d += 1024) {
        float4 hv = *(const float4*)(g_h + hb + d);
        float4 a  = *(const float4*)(g_op + (size_t)p0 * D_ + d);
        float4 b4 = *(const float4*)(g_op + (size_t)p1 * D_ + d);
        float4 o;
        o.x = hv.x + w0 * a.x + w1 * b4.x;
        o.y = hv.y + w0 * a.y + w1 * b4.y;
        o.z = hv.z + w0 * a.z + w1 * b4.z;
        o.w = hv.w + w0 * a.w + w1 * b4.w;
        *(float4*)(out + hb + d) = o;
    }
}

// ---------------- launcher ----------------
extern "C" void kernel_launch(void* const* d_in, const int* in_sizes, int n_in,
                              void* d_out, int out_size) {
    const float* hidden = (const float*)d_in[0];
    const float* ln1    = (const float*)d_in[1];
    const float* ln2    = (const float*)d_in[2];
    const float* qw     = (const float*)d_in[3];
    const float* kw     = (const float*)d_in[4];
    const float* vw     = (const float*)d_in[5];
    const float* ow     = (const float*)d_in[6];
    const float* gw     = (const float*)d_in[7];
    const float* egw    = (const float*)d_in[8];
    const float* euw    = (const float*)d_in[9];
    const float* edw    = (const float*)d_in[10];
    const int*   pos    = (const int*)d_in[11];
    float* out = (float*)d_out;

    float *qb, *kb, *vb, *hb, *x2, *gb, *ub, *op;
    cudaGetSymbolAddress((void**)&qb, g_q);
    cudaGetSymbolAddress((void**)&kb, g_k);
    cudaGetSymbolAddress((void**)&vb, g_v);
    cudaGetSymbolAddress((void**)&hb, g_h);
    cudaGetSymbolAddress((void**)&x2, g_xn2);
    cudaGetSymbolAddress((void**)&gb, g_gb);
    cudaGetSymbolAddress((void**)&ub, g_ub);
    cudaGetSymbolAddress((void**)&op, g_op);

    bf16 *xnh, *xnl, *ah, *al, *x2h, *x2l, *ih, *il;
    bf16 *wqh, *wql, *wkh, *wkl, *wvh, *wvl, *woh, *wol;
    bf16 *egh, *egl, *euh, *eul, *edh, *edl;
    cudaGetSymbolAddress((void**)&xnh, g_xnh); cudaGetSymbolAddress((void**)&xnl, g_xnl);
    cudaGetSymbolAddress((void**)&ah,  g_ah);  cudaGetSymbolAddress((void**)&al,  g_al);
    cudaGetSymbolAddress((void**)&x2h, g_x2h); cudaGetSymbolAddress((void**)&x2l, g_x2l);
    cudaGetSymbolAddress((void**)&ih,  g_ih);  cudaGetSymbolAddress((void**)&il,  g_il);
    cudaGetSymbolAddress((void**)&wqh, g_wqh); cudaGetSymbolAddress((void**)&wql, g_wql);
    cudaGetSymbolAddress((void**)&wkh, g_wkh); cudaGetSymbolAddress((void**)&wkl, g_wkl);
    cudaGetSymbolAddress((void**)&wvh, g_wvh); cudaGetSymbolAddress((void**)&wvl, g_wvl);
    cudaGetSymbolAddress((void**)&woh, g_woh); cudaGetSymbolAddress((void**)&wol, g_wol);
    cudaGetSymbolAddress((void**)&egh, g_egh); cudaGetSymbolAddress((void**)&egl, g_egl);
    cudaGetSymbolAddress((void**)&euh, g_euh); cudaGetSymbolAddress((void**)&eul, g_eul);
    cudaGetSymbolAddress((void**)&edh, g_edh); cudaGetSymbolAddress((void**)&edl, g_edl);

    // 0. per-call weight split (DRAM-bound, ~115us total)
    splitw_k<<<512, 256>>>(qw,  wqh, wql, D_*D_/4);
    splitw_k<<<512, 256>>>(kw,  wkh, wkl, D_*D_/4);
    splitw_k<<<512, 256>>>(vw,  wvh, wvl, D_*D_/4);
    splitw_k<<<512, 256>>>(ow,  woh, wol, D_*D_/4);
    splitw_k<<<1024, 256>>>(egw, egh, egl, EE*DE_*D_/4);
    splitw_k<<<1024, 256>>>(euw, euh, eul, EE*DE_*D_/4);
    splitw_k<<<1024, 256>>>(edw, edh, edl, EE*D_*DE_/4);

    // 1. pre-attention RMSNorm (split output)
    rmsnorm_sp_k<<<NTOK, 256>>>(hidden, ln1, nullptr, xnh, xnl);

    // 2. fused QKV projection
    gemm_bfp<0, 1><<<dim3(48, NTOK / TM, 1), 256>>>(
        xnh, xnl, wqh, wql, qb, nullptr, NTOK, D_, D_, 0,
        wkh, wkl, kb, wvh, wvl, vb);

    // 3. fused RoPE + Q/K split, V split/transpose
    rope_split_k<<<(NTOK * HN * 64) / 256, 256>>>(pos);
    splitv_k<<<dim3(SQ / 32, HD / 32, BB * HN), dim3(32, 8)>>>();

    // 4. smem-staged mma flash attention (writes hi/lo planes)
    attn_mma_k<<<dim3(SQ / 64, HN, BB), 128>>>();

    // 5. O projection + residual
    gemm_bfp<0><<<dim3(D_ / TN, NTOK / TM, 1), 256>>>(
        ah, al, woh, wol, hb, hidden, NTOK, D_, D_, 0,
        nullptr, nullptr, nullptr, nullptr, nullptr, nullptr);

    // 6. post-attention RMSNorm (fp32 for routing + planes for GEMMs)
    rmsnorm_sp_k<<<NTOK, 256>>>(hb, ln2, x2, x2h, x2l);

    // 7. routing
    zero_k<<<1, 32>>>();
    route1_k<<<NTOK, 256>>>(x2, gw);
    scan_k<<<1, 1>>>();
    assign_k<<<NTOK / 256, 256>>>();

    // 8. MoE expert GEMMs: fused gate+up, then down
    gemm_bfp<1, 2><<<dim3(12, 16, EE), 256>>>(
        x2h, x2l, egh, egl, gb, nullptr, 0, DE_, D_, (long)DE_ * D_,
        euh, eul, ub, nullptr, nullptr, nullptr);
    swiglu_k<<<(NSLOT * DE_ + 255) / 256, 256>>>();
    gemm_bfp<2><<<dim3(D_ / TN, 16, EE), 256>>>(
        ih, il, edh, edl, op, nullptr, 0, D_, DE_, (long)D_ * DE_,
        nullptr, nullptr, nullptr, nullptr, nullptr, nullptr);

    // 9. weighted combine + residual
    final_k<<<NTOK, 256>>>(out);
}

// round 16
// speedup vs baseline: 1.7281x; 1.7281x over previous
#include <cuda_runtime.h>
#include <cuda_bf16.h>
#include <math.h>
#include <stdint.h>

// ---------------- problem constants ----------------
#define BB 2
#define SQ 1024
#define D_ 2048
#define HN 16
#define HD 128
#define NTOK (BB*SQ)       // 2048
#define EE 8
#define DE_ 704
#define NSLOT (NTOK*2)     // 4096 (top-2 per token)

typedef __nv_bfloat16 bf16;

// ---------------- scratch (device globals: no allocations allowed) ----------------
__device__ float g_q   [NTOK*D_];
__device__ float g_k   [NTOK*D_];
__device__ float g_v   [NTOK*D_];
__device__ float g_h   [NTOK*D_];
__device__ float g_xn2 [NTOK*D_];
__device__ float g_gb  [NSLOT*DE_];
__device__ float g_ub  [NSLOT*DE_];
__device__ float g_op  [NSLOT*D_];
__device__ int   g_cnt [EE];
__device__ int   g_cur [EE];
__device__ int   g_off [EE];
__device__ int   g_tope[NTOK*2];
__device__ float g_topw[NTOK*2];
__device__ int   g_slot_tok[NSLOT];
__device__ float g_slot_w  [NSLOT];
__device__ int   g_tok_pos [NTOK*2];
// bf16 hi/lo activation planes (produced for free by producer kernels)
__device__ bf16 g_xnh[NTOK*D_],  g_xnl[NTOK*D_];    // pre-attn norm out
__device__ bf16 g_qh [NTOK*D_],  g_ql [NTOK*D_];
__device__ bf16 g_kh [NTOK*D_],  g_kl [NTOK*D_];
__device__ bf16 g_vth[NTOK*D_],  g_vtl[NTOK*D_];    // V transposed [bh][HD][SQ]
__device__ bf16 g_ah [NTOK*D_],  g_al [NTOK*D_];    // attention out planes
__device__ bf16 g_x2h[NTOK*D_],  g_x2l[NTOK*D_];    // post-attn norm out
__device__ bf16 g_ih [NSLOT*DE_], g_il [NSLOT*DE_]; // swiglu inter planes

// ---------------- helpers ----------------
__device__ __forceinline__ uint32_t smem_u32(const void* p) {
    uint32_t a;
    asm("{ .reg .u64 t; cvta.to.shared.u64 t, %1; cvt.u32.u64 %0, t; }" : "=r"(a) : "l"(p));
    return a;
}
__device__ __forceinline__ void mma_bf16(float* c, const uint32_t* a,
                                         uint32_t b0, uint32_t b1) {
    asm volatile(
        "mma.sync.aligned.m16n8k16.row.col.f32.bf16.bf16.f32 "
        "{%0,%1,%2,%3}, {%4,%5,%6,%7}, {%8,%9}, {%0,%1,%2,%3};"
        : "+f"(c[0]), "+f"(c[1]), "+f"(c[2]), "+f"(c[3])
        : "r"(a[0]), "r"(a[1]), "r"(a[2]), "r"(a[3]), "r"(b0), "r"(b1));
}
__device__ __forceinline__ void ldsm4(uint32_t& r0, uint32_t& r1, uint32_t& r2,
                                      uint32_t& r3, uint32_t addr) {
    asm volatile("ldmatrix.sync.aligned.m8n8.x4.shared.b16 {%0,%1,%2,%3}, [%4];"
                 : "=r"(r0), "=r"(r1), "=r"(r2), "=r"(r3) : "r"(addr));
}
__device__ __forceinline__ void split2(float x0, float x1, uint32_t& wh, uint32_t& wl) {
    bf16 h0 = __float2bfloat16(x0);
    bf16 h1 = __float2bfloat16(x1);
    bf16 l0 = __float2bfloat16(x0 - __bfloat162float(h0));
    bf16 l1 = __float2bfloat16(x1 - __bfloat162float(h1));
    wh = ((uint32_t)__bfloat16_as_ushort(h1) << 16) | __bfloat16_as_ushort(h0);
    wl = ((uint32_t)__bfloat16_as_ushort(l1) << 16) | __bfloat16_as_ushort(l0);
}
__device__ __forceinline__ void split1(float x, bf16& h, bf16& l) {
    h = __float2bfloat16(x);
    l = __float2bfloat16(x - __bfloat162float(h));
}
__device__ __forceinline__ void cpa16(uint32_t dst, const void* src) {
    asm volatile("cp.async.ca.shared.global [%0], [%1], 16;" :: "r"(dst), "l"(src));
}
#define CP_COMMIT() asm volatile("cp.async.commit_group;" ::: "memory")
#define CP_WAIT0()  asm volatile("cp.async.wait_group 0;" ::: "memory")

// ---------------- hybrid tensor GEMM ----------------
// C[M,N] = A[M,K] * W[N,K]^T (+add).
// A given as bf16 hi/lo planes (AH/AL); W fp32, split in-kernel (R13 pipeline).
// MODE 0: dense. MODE 1: A rows gathered via g_slot_tok. MODE 2: A rows contiguous.
// FUSE 1: QKV (blockIdx.x/16 selects W/C). FUSE 2: gate+up (x>=6 -> W2/C2).
#define TM 128
#define TN 128
#define BK 16
#define RS 12   // row stride in 32-bit words (48B) -> conflict-free for ldmatrix

template<int MODE, int FUSE = 0>
__global__ void __launch_bounds__(256) gemm_hy(
    const bf16* __restrict__ AH, const bf16* __restrict__ AL,
    const float* __restrict__ W,
    float* __restrict__ C, const float* __restrict__ addp,
    int M, int Nn, int Kk, long wstride,
    const float* __restrict__ W2, float* __restrict__ C2,
    const float* __restrict__ W3, float* __restrict__ C3)
{
    __shared__ uint32_t AhS[2][TM][RS];
    __shared__ uint32_t AlS[2][TM][RS];
    __shared__ uint32_t BhS[2][TN][RS];
    __shared__ uint32_t BlS[2][TN][RS];

    int e = blockIdx.z;
    int Mloc = M, base = 0;
    int bx = blockIdx.x;
    const float* Wb = W;
    float* Cp = C;
    if (FUSE == 1) {
        int sel = bx >> 4; bx &= 15;
        Wb = (sel == 0) ? W : ((sel == 1) ? W2 : W3);
        Cp = (sel == 0) ? C : ((sel == 1) ? C2 : C3);
    }
    if (FUSE == 2) {
        if (bx >= 6) { bx -= 6; Wb = W2; Cp = C2; }
    }
    const float* Wp = Wb;
    if (MODE != 0) { Mloc = g_cnt[e]; base = g_off[e]; Wp = Wb + (size_t)e * (size_t)wstride; }
    int m0 = blockIdx.y * TM;
    if (m0 >= Mloc) return;
    int n0 = bx * TN;
    int tid = threadIdx.x;

    // ---- A staging: thread -> (row = tid>>1, 16B chunk = tid&1), bf16 planes ----
    int srow = tid >> 1, ch = tid & 1;
    uint32_t aSmemOff = (uint32_t)(srow * 48 + ch * 16);
    int gm = m0 + srow;
    bool av = gm < Mloc;
    int arow;
    if (MODE == 0)      arow = av ? gm : 0;
    else if (MODE == 1) arow = av ? g_slot_tok[base + gm] : 0;
    else                arow = av ? (base + gm) : 0;
    const bf16* pAh = AH + (size_t)arow * Kk + ch * 8;
    const bf16* pAl = AL + (size_t)arow * Kk + ch * 8;

    // ---- B staging: 2 slots per thread (R13 scheme), fp32 + in-kernel split ----
    const float* bP[2];
    int rowL[2], c4L[2];
    bool bV[2];
#pragma unroll
    for (int i = 0; i < 2; i++) {
        int v = tid + i * 256;
        int row = v >> 2, c4 = v & 3;
        rowL[i] = row; c4L[i] = c4;
        int gn = n0 + row;
        bV[i] = gn < Nn;
        bP[i] = Wp + (size_t)(bV[i] ? gn : 0) * Kk + c4 * 4;
    }

    int lane = tid & 31, g = lane >> 2, tg = lane & 3;
    int wm = (tid >> 5) & 3;
    int wn = tid >> 7;
    int mbase = wm * 32, nbase = wn * 64;

    uint32_t sAh = smem_u32(AhS), sAl = smem_u32(AlS);
    uint32_t sBh = smem_u32(BhS), sBl = smem_u32(BlS);
    uint32_t aoff[2], boff[4];
#pragma unroll
    for (int mt = 0; mt < 2; mt++)
        aoff[mt] = (uint32_t)((mbase + mt * 16 + (lane & 7) + ((lane >> 3) & 1) * 8) * 48
                              + ((lane >> 4) & 1) * 16);
#pragma unroll
    for (int p = 0; p < 4; p++)
        boff[p] = (uint32_t)((nbase + p * 16 + (lane & 7) + ((lane >> 4) & 1) * 8) * 48
                             + ((lane >> 3) & 1) * 16);

    float acc[2][8][4];
#pragma unroll
    for (int mt = 0; mt < 2; mt++)
#pragma unroll
        for (int nt = 0; nt < 8; nt++)
#pragma unroll
            for (int q = 0; q < 4; q++) acc[mt][nt][q] = 0.f;

    int nk = Kk / BK;
    uint4 rAh, rAl;
    float4 rb[2];
    const uint4 z4 = make_uint4(0, 0, 0, 0);
    rAh = av ? *(const uint4*)(pAh) : z4;
    rAl = av ? *(const uint4*)(pAl) : z4;
#pragma unroll
    for (int i = 0; i < 2; i++)
        rb[i] = bV[i] ? *(const float4*)(bP[i]) : make_float4(0,0,0,0);

    int buf = 0;
    for (int it = 0; it < nk; it++) {
        // ---- store current regs to smem ----
        *(uint4*)((uint8_t*)AhS + (size_t)buf * (TM*RS*4) + aSmemOff) = rAh;
        *(uint4*)((uint8_t*)AlS + (size_t)buf * (TM*RS*4) + aSmemOff) = rAl;
#pragma unroll
        for (int i = 0; i < 2; i++) {
            int r = rowL[i], w0 = c4L[i] * 2;
            uint32_t h0, l0, h1, l1;
            split2(rb[i].x, rb[i].y, h0, l0);
            split2(rb[i].z, rb[i].w, h1, l1);
            BhS[buf][r][w0] = h0; BhS[buf][r][w0+1] = h1;
            BlS[buf][r][w0] = l0; BlS[buf][r][w0+1] = l1;
        }
        // ---- prefetch next stage ----
        if (it + 1 < nk) {
            int k0 = (it + 1) * BK;
            rAh = av ? *(const uint4*)(pAh + k0) : z4;
            rAl = av ? *(const uint4*)(pAl + k0) : z4;
#pragma unroll
            for (int i = 0; i < 2; i++)
                rb[i] = bV[i] ? *(const float4*)(bP[i] + k0) : make_float4(0,0,0,0);
        }
        __syncthreads();

        // ---- compute from buf ----
        uint32_t bufo = (uint32_t)buf * (TM * RS * 4);
        uint32_t ah[2][4], al[2][4];
#pragma unroll
        for (int mt = 0; mt < 2; mt++) {
            ldsm4(ah[mt][0], ah[mt][1], ah[mt][2], ah[mt][3], sAh + bufo + aoff[mt]);
            ldsm4(al[mt][0], al[mt][1], al[mt][2], al[mt][3], sAl + bufo + aoff[mt]);
        }
#pragma unroll
        for (int p = 0; p < 4; p++) {
            uint32_t b00, b01, b10, b11, c00, c01, c10, c11;
            ldsm4(b00, b01, b10, b11, sBh + bufo + boff[p]);
            ldsm4(c00, c01, c10, c11, sBl + bufo + boff[p]);
#pragma unroll
            for (int mt = 0; mt < 2; mt++) {
                mma_bf16(acc[mt][2*p],   ah[mt], b00, b01);
                mma_bf16(acc[mt][2*p],   ah[mt], c00, c01);
                mma_bf16(acc[mt][2*p],   al[mt], b00, b01);
                mma_bf16(acc[mt][2*p+1], ah[mt], b10, b11);
                mma_bf16(acc[mt][2*p+1], ah[mt], c10, c11);
                mma_bf16(acc[mt][2*p+1], al[mt], b10, b11);
            }
        }
        buf ^= 1;
        // single barrier per stage safe with 2 buffers: writes at iter it target
        // the buffer read at it-1? no — buffer written at it is computed at it
        // (post-sync); the pre-sync writes never touch the buffer a straggler
        // warp is reading (that is buf^1, written/computed at it-1).
    }

    // ---- epilogue: c0/c1 -> (row g, cols 2tg,2tg+1), c2/c3 -> row g+8 ----
#pragma unroll
    for (int mt = 0; mt < 2; mt++) {
#pragma unroll
        for (int nt = 0; nt < 8; nt++) {
            int gc = n0 + nbase + nt * 8 + tg * 2;
            if (gc >= Nn) continue;
            int gm0 = m0 + mbase + mt * 16 + g;
#pragma unroll
            for (int hrow = 0; hrow < 2; hrow++) {
                int gmr = gm0 + hrow * 8;
                if (gmr >= Mloc) continue;
                int crow = (MODE == 0) ? gmr : (base + gmr);
                size_t off = (size_t)crow * Nn + gc;
                float2 vv = make_float2(acc[mt][nt][hrow * 2], acc[mt][nt][hrow * 2 + 1]);
                if (MODE == 0 && addp) {
                    float2 rv = *(const float2*)(addp + off);
                    vv.x += rv.x; vv.y += rv.y;
                }
                *(float2*)(Cp + off) = vv;
            }
        }
    }
}

// ---------------- RMSNorm with split output ----------------
__global__ void rmsnorm_sp_k(const float* __restrict__ x, const float* __restrict__ w,
                             float* __restrict__ o, bf16* __restrict__ oh,
                             bf16* __restrict__ ol) {
    int n = blockIdx.x;
    const float* xr = x + (size_t)n * D_;
    float s = 0.f;
    for (int d = threadIdx.x; d < D_; d += 256) { float v = xr[d]; s += v * v; }
    __shared__ float red[256];
    red[threadIdx.x] = s; __syncthreads();
    for (int st = 128; st > 0; st >>= 1) {
        if (threadIdx.x < st) red[threadIdx.x] += red[threadIdx.x + st];
        __syncthreads();
    }
    float inv = rsqrtf(red[0] / (float)D_ + 1e-6f);
    size_t ro = (size_t)n * D_;
    for (int d = threadIdx.x; d < D_; d += 256) {
        float v = xr[d] * inv * w[d];
        if (o) o[ro + d] = v;
        bf16 h, l;
        split1(v, h, l);
        oh[ro + d] = h; ol[ro + d] = l;
    }
}

// ---------------- fused RoPE + bf16 hi/lo split for Q,K ----------------
__global__ void rope_split_k(const int* __restrict__ pos) {
    int idx = blockIdx.x * 256 + threadIdx.x;
    if (idx >= NTOK * HN * 64) return;
    int j  = idx & 63;
    int hh = (idx >> 6) & 15;
    int t  = idx >> 10;
    float p = (float)pos[t];
    float inv = expf(-((float)(2 * j) / 128.0f) * 9.210340371976184f);
    float fr = p * inv;
    float sn, cs;
    sincosf(fr, &sn, &cs);
    size_t base = (size_t)t * D_ + hh * HD + j;
    bf16 h, l;
    float x1 = g_q[base], x2 = g_q[base + 64];
    float r1 = x1 * cs - x2 * sn, r2 = x2 * cs + x1 * sn;
    split1(r1, h, l); g_qh[base] = h;      g_ql[base] = l;
    split1(r2, h, l); g_qh[base + 64] = h; g_ql[base + 64] = l;
    x1 = g_k[base]; x2 = g_k[base + 64];
    r1 = x1 * cs - x2 * sn; r2 = x2 * cs + x1 * sn;
    split1(r1, h, l); g_kh[base] = h;      g_kl[base] = l;
    split1(r2, h, l); g_kh[base + 64] = h; g_kl[base + 64] = l;
}

// ---------------- split V + transpose to [bh][dim][seq] bf16 hi/lo ----------------
__global__ void splitv_k() {
    __shared__ bf16 sh[32][33], sl[32][33];
    int tx = threadIdx.x, ty = threadIdx.y;      // (32, 8)
    int s0 = blockIdx.x * 32;
    int d0 = blockIdx.y * 32;
    int bh = blockIdx.z;
    int b = bh >> 4, hh = bh & 15;
#pragma unroll
    for (int i = 0; i < 4; i++) {
        int sr = ty + i * 8;
        float v = g_v[((size_t)(b * SQ + s0 + sr)) * D_ + hh * HD + d0 + tx];
        bf16 h, l;
        split1(v, h, l);
        sh[sr][tx] = h; sl[sr][tx] = l;
    }
    __syncthreads();
#pragma unroll
    for (int i = 0; i < 4; i++) {
        int dr = ty + i * 8;
        size_t o = ((size_t)bh * HD + d0 + dr) * SQ + s0 + tx;
        g_vth[o] = sh[tx][dr];
        g_vtl[o] = sl[tx][dr];
    }
}

// ---------------- flash attention: smem-staged K/V + mma.sync bf16x3 ----------------
// grid (SQ/64, HN, BB), block 128. Epilogue writes bf16 hi/lo planes for O-proj.
__global__ void __launch_bounds__(128) attn_mma_k()
{
    __shared__ __align__(16) uint8_t sm[49152];
    uint32_t sb = smem_u32(sm);
    int tid = threadIdx.x;
    int w = tid >> 5, lane = tid & 31;
    int g = lane >> 2, tg = lane & 3;
    int hh = blockIdx.y, b = blockIdx.z;
    int qsb = blockIdx.x * 64;
    int qs0 = qsb + w * 16;
    int bh = b * HN + hh;

    uint32_t qfh[8][4], qfl[8][4];
    size_t qr0 = ((size_t)(b * SQ + qs0 + g)) * D_ + hh * HD;
    size_t qr1 = qr0 + (size_t)8 * D_;
#pragma unroll
    for (int ks = 0; ks < 8; ks++) {
        int c0 = ks * 16 + 2 * tg;
        qfh[ks][0] = *(const uint32_t*)&g_qh[qr0 + c0];
        qfh[ks][1] = *(const uint32_t*)&g_qh[qr1 + c0];
        qfh[ks][2] = *(const uint32_t*)&g_qh[qr0 + c0 + 8];
        qfh[ks][3] = *(const uint32_t*)&g_qh[qr1 + c0 + 8];
        qfl[ks][0] = *(const uint32_t*)&g_ql[qr0 + c0];
        qfl[ks][1] = *(const uint32_t*)&g_ql[qr1 + c0];
        qfl[ks][2] = *(const uint32_t*)&g_ql[qr0 + c0 + 8];
        qfl[ks][3] = *(const uint32_t*)&g_ql[qr1 + c0 + 8];
    }

    uint32_t lm_row = (lane & 7) + ((lane >> 4) & 1) * 8;
    uint32_t lm_col = ((lane >> 3) & 1) * 16;

    float m0 = -1e30f, m1 = -1e30f, l0 = 0.f, l1 = 0.f;
    float Oa[16][4];
#pragma unroll
    for (int nt = 0; nt < 16; nt++)
#pragma unroll
        for (int q = 0; q < 4; q++) Oa[nt][q] = 0.f;

    const float SC = 0.08838834764831845f;
    int row0 = qs0 + g, row1 = row0 + 8;
    int nsteps = qsb / 32 + 2;

    for (int step = 0; step < nsteps; step++) {
        int kt = step * 32;
        {
            size_t kg = ((size_t)(b * SQ + kt)) * D_ + hh * HD;
#pragma unroll
            for (int i = 0; i < 4; i++) {
                int idx = tid * 4 + i;
                int tok = idx >> 4, ks = (idx >> 1) & 7, c = idx & 1;
                size_t so = kg + (size_t)tok * D_ + ks * 16 + c * 8;
                uint32_t dst = sb + (uint32_t)(ks * 1536 + tok * 48 + c * 16);
                cpa16(dst,         g_kh + so);
                cpa16(dst + 12288, g_kl + so);
            }
            size_t vg = (size_t)bh * HD * SQ + kt;
#pragma unroll
            for (int i = 0; i < 4; i++) {
                int idx = tid * 4 + i;
                int dim = idx >> 2, ks2 = (idx >> 1) & 1, c = idx & 1;
                size_t so = vg + (size_t)dim * SQ + ks2 * 16 + c * 8;
                uint32_t dst = sb + 24576u + (uint32_t)(ks2 * 6144 + dim * 48 + c * 16);
                cpa16(dst,         g_vth + so);
                cpa16(dst + 12288, g_vtl + so);
            }
        }
        CP_COMMIT();
        CP_WAIT0();
        __syncthreads();

        float s[4][4];
#pragma unroll
        for (int nt = 0; nt < 4; nt++)
#pragma unroll
            for (int q = 0; q < 4; q++) s[nt][q] = 0.f;

#pragma unroll
        for (int ks = 0; ks < 8; ks++) {
#pragma unroll
            for (int p = 0; p < 2; p++) {
                uint32_t ka = sb + (uint32_t)(ks * 1536 + (p * 16 + lm_row) * 48) + lm_col;
                uint32_t b00, b01, b10, b11, c00, c01, c10, c11;
                ldsm4(b00, b01, b10, b11, ka);
                ldsm4(c00, c01, c10, c11, ka + 12288);
                mma_bf16(s[2*p],   qfh[ks], b00, b01);
                mma_bf16(s[2*p],   qfh[ks], c00, c01);
                mma_bf16(s[2*p],   qfl[ks], b00, b01);
                mma_bf16(s[2*p+1], qfh[ks], b10, b11);
                mma_bf16(s[2*p+1], qfh[ks], c10, c11);
                mma_bf16(s[2*p+1], qfl[ks], b10, b11);
            }
        }

#pragma unroll
        for (int nt = 0; nt < 4; nt++) {
            int col = kt + nt * 8 + 2 * tg;
            s[nt][0] = (col     <= row0) ? s[nt][0] * SC : -1e30f;
            s[nt][1] = (col + 1 <= row0) ? s[nt][1] * SC : -1e30f;
            s[nt][2] = (col     <= row1) ? s[nt][2] * SC : -1e30f;
            s[nt][3] = (col + 1 <= row1) ? s[nt][3] * SC : -1e30f;
        }

        float mx0 = -1e30f, mx1 = -1e30f;
#pragma unroll
        for (int nt = 0; nt < 4; nt++) {
            mx0 = fmaxf(mx0, fmaxf(s[nt][0], s[nt][1]));
            mx1 = fmaxf(mx1, fmaxf(s[nt][2], s[nt][3]));
        }
        mx0 = fmaxf(mx0, __shfl_xor_sync(0xffffffff, mx0, 1));
        mx0 = fmaxf(mx0, __shfl_xor_sync(0xffffffff, mx0, 2));
        mx1 = fmaxf(mx1, __shfl_xor_sync(0xffffffff, mx1, 1));
        mx1 = fmaxf(mx1, __shfl_xor_sync(0xffffffff, mx1, 2));
        float mn0 = fmaxf(m0, mx0), mn1 = fmaxf(m1, mx1);
        float a0 = __expf(m0 - mn0), a1 = __expf(m1 - mn1);
        float sum0 = 0.f, sum1 = 0.f;
#pragma unroll
        for (int nt = 0; nt < 4; nt++) {
            s[nt][0] = __expf(s[nt][0] - mn0);
            s[nt][1] = __expf(s[nt][1] - mn0);
            s[nt][2] = __expf(s[nt][2] - mn1);
            s[nt][3] = __expf(s[nt][3] - mn1);
            sum0 += s[nt][0] + s[nt][1];
            sum1 += s[nt][2] + s[nt][3];
        }
        sum0 += __shfl_xor_sync(0xffffffff, sum0, 1);
        sum0 += __shfl_xor_sync(0xffffffff, sum0, 2);
        sum1 += __shfl_xor_sync(0xffffffff, sum1, 1);
        sum1 += __shfl_xor_sync(0xffffffff, sum1, 2);
        l0 = l0 * a0 + sum0; l1 = l1 * a1 + sum1;
        m0 = mn0; m1 = mn1;

#pragma unroll
        for (int nt = 0; nt < 16; nt++) {
            Oa[nt][0] *= a0; Oa[nt][1] *= a0;
            Oa[nt][2] *= a1; Oa[nt][3] *= a1;
        }

        uint32_t pah[2][4], pal[2][4];
#pragma unroll
        for (int ks2 = 0; ks2 < 2; ks2++) {
            int na = ks2 * 2, nb = na + 1;
            split2(s[na][0], s[na][1], pah[ks2][0], pal[ks2][0]);
            split2(s[na][2], s[na][3], pah[ks2][1], pal[ks2][1]);
            split2(s[nb][0], s[nb][1], pah[ks2][2], pal[ks2][2]);
            split2(s[nb][2], s[nb][3], pah[ks2][3], pal[ks2][3]);
        }

#pragma unroll
        for (int ks2 = 0; ks2 < 2; ks2++) {
#pragma unroll
            for (int p = 0; p < 8; p++) {
                uint32_t va = sb + 24576u
                            + (uint32_t)(ks2 * 6144 + (p * 16 + lm_row) * 48) + lm_col;
                uint32_t v00, v01, v10, v11, u00, u01, u10, u11;
                ldsm4(v00, v01, v10, v11, va);
                ldsm4(u00, u01, u10, u11, va + 12288);
                mma_bf16(Oa[2*p],   pah[ks2], v00, v01);
                mma_bf16(Oa[2*p],   pah[ks2], u00, u01);
                mma_bf16(Oa[2*p],   pal[ks2], v00, v01);
                mma_bf16(Oa[2*p+1], pah[ks2], v10, v11);
                mma_bf16(Oa[2*p+1], pah[ks2], u10, u11);
                mma_bf16(Oa[2*p+1], pal[ks2], v10, v11);
            }
        }
        __syncthreads();
    }

    // epilogue: write bf16 hi/lo planes for the O-projection GEMM
    float i0 = 1.f / l0, i1 = 1.f / l1;
    size_t or0 = ((size_t)(b * SQ + qs0 + g)) * D_ + hh * HD;
    size_t or1 = or0 + (size_t)8 * D_;
#pragma unroll
    for (int nt = 0; nt < 16; nt++) {
        int col = nt * 8 + 2 * tg;
        uint32_t h, l;
        split2(Oa[nt][0] * i0, Oa[nt][1] * i0, h, l);
        *(uint32_t*)&g_ah[or0 + col] = h;
        *(uint32_t*)&g_al[or0 + col] = l;
        split2(Oa[nt][2] * i1, Oa[nt][3] * i1, h, l);
        *(uint32_t*)&g_ah[or1 + col] = h;
        *(uint32_t*)&g_al[or1 + col] = l;
    }
}

// ---------------- MoE routing ----------------
__global__ void zero_k() {
    if (threadIdx.x < EE) { g_cnt[threadIdx.x] = 0; g_cur[threadIdx.x] = 0; }
}

__global__ void route1_k(const float* __restrict__ x, const float* __restrict__ gw) {
    int n = blockIdx.x;
    float part[EE];
#pragma unroll
    for (int e = 0; e < EE; e++) part[e] = 0.f;
    for (int d = threadIdx.x; d < D_; d += 256) {
        float xv = x[(size_t)n * D_ + d];
#pragma unroll
        for (int e = 0; e < EE; e++) part[e] = fmaf(xv, gw[e * D_ + d], part[e]);
    }
    __shared__ float red[256];
    __shared__ float lg[EE];
    for (int e = 0; e < EE; e++) {
        red[threadIdx.x] = part[e]; __syncthreads();
        for (int st = 128; st > 0; st >>= 1) {
            if (threadIdx.x < st) red[threadIdx.x] += red[threadIdx.x + st];
            __syncthreads();
        }
        if (threadIdx.x == 0) lg[e] = red[0];
        __syncthreads();
    }
    if (threadIdx.x == 0) {
        int i0 = 0; float b0 = lg[0];
        for (int e = 1; e < EE; e++) if (lg[e] > b0) { b0 = lg[e]; i0 = e; }
        int i1 = -1; float b1 = -1e30f;
        for (int e = 0; e < EE; e++) { if (e == i0) continue; if (lg[e] > b1) { b1 = lg[e]; i1 = e; } }
        float m = fmaxf(b0, b1);
        float w0 = __expf(b0 - m), w1 = __expf(b1 - m);
        float s = w0 + w1; w0 /= s; w1 /= s;
        g_tope[n*2] = i0; g_tope[n*2+1] = i1;
        g_topw[n*2] = w0; g_topw[n*2+1] = w1;
        atomicAdd(&g_cnt[i0], 1); atomicAdd(&g_cnt[i1], 1);
    }
}

__global__ void scan_k() {
    int o = 0;
    for (int e = 0; e < EE; e++) { g_off[e] = o; o += g_cnt[e]; }
}

__global__ void assign_k() {
    int n = blockIdx.x * 256 + threadIdx.x;
    if (n >= NTOK) return;
#pragma unroll
    for (int kk = 0; kk < 2; kk++) {
        int e = g_tope[n*2 + kk];
        int p = g_off[e] + atomicAdd(&g_cur[e], 1);
        g_slot_tok[p] = n;
        g_slot_w[p]   = g_topw[n*2 + kk];
        g_tok_pos[n*2 + kk] = p;
    }
}

// ---------------- swiglu with split (plane) output ----------------
__global__ void swiglu_k() {
    int i = blockIdx.x * 256 + threadIdx.x;
    if (i >= NSLOT * DE_) return;
    float g = g_gb[i], u = g_ub[i];
    float sig = 1.f / (1.f + __expf(-g));
    float v = g * sig * u;
    bf16 h, l;
    split1(v, h, l);
    g_ih[i] = h; g_il[i] = l;
}

__global__ void final_k(float* __restrict__ out) {
    int n = blockIdx.x;
    int p0 = g_tok_pos[n*2], p1 = g_tok_pos[n*2 + 1];
    float w0 = g_slot_w[p0], w1 = g_slot_w[p1];
    size_t hb = (size_t)n * D_;
    for (int d = threadIdx.x * 4; d < D_; d += 1024) {
        float4 hv = *(const float4*)(g_h + hb + d);
        float4 a  = *(const float4*)(g_op + (size_t)p0 * D_ + d);
        float4 b4 = *(const float4*)(g_op + (size_t)p1 * D_ + d);
        float4 o;
        o.x = hv.x + w0 * a.x + w1 * b4.x;
        o.y = hv.y + w0 * a.y + w1 * b4.y;
        o.z = hv.z + w0 * a.z + w1 * b4.z;
        o.w = hv.w + w0 * a.w + w1 * b4.w;
        *(float4*)(out + hb + d) = o;
    }
}

// ---------------- launcher ----------------
extern "C" void kernel_launch(void* const* d_in, const int* in_sizes, int n_in,
                              void* d_out, int out_size) {
    const float* hidden = (const float*)d_in[0];
    const float* ln1    = (const float*)d_in[1];
    const float* ln2    = (const float*)d_in[2];
    const float* qw     = (const float*)d_in[3];
    const float* kw     = (const float*)d_in[4];
    const float* vw     = (const float*)d_in[5];
    const float* ow     = (const float*)d_in[6];
    const float* gw     = (const float*)d_in[7];
    const float* egw    = (const float*)d_in[8];
    const float* euw    = (const float*)d_in[9];
    const float* edw    = (const float*)d_in[10];
    const int*   pos    = (const int*)d_in[11];
    float* out = (float*)d_out;

    float *qb, *kb, *vb, *hb, *x2, *gb, *ub, *op;
    cudaGetSymbolAddress((void**)&qb, g_q);
    cudaGetSymbolAddress((void**)&kb, g_k);
    cudaGetSymbolAddress((void**)&vb, g_v);
    cudaGetSymbolAddress((void**)&hb, g_h);
    cudaGetSymbolAddress((void**)&x2, g_xn2);
    cudaGetSymbolAddress((void**)&gb, g_gb);
    cudaGetSymbolAddress((void**)&ub, g_ub);
    cudaGetSymbolAddress((void**)&op, g_op);

    bf16 *xnh, *xnl, *ah, *al, *x2h, *x2l, *ih, *il;
    cudaGetSymbolAddress((void**)&xnh, g_xnh); cudaGetSymbolAddress((void**)&xnl, g_xnl);
    cudaGetSymbolAddress((void**)&ah,  g_ah);  cudaGetSymbolAddress((void**)&al,  g_al);
    cudaGetSymbolAddress((void**)&x2h, g_x2h); cudaGetSymbolAddress((void**)&x2l, g_x2l);
    cudaGetSymbolAddress((void**)&ih,  g_ih);  cudaGetSymbolAddress((void**)&il,  g_il);

    // 1. pre-attention RMSNorm (emit bf16 hi/lo planes only)
    rmsnorm_sp_k<<<NTOK, 256>>>(hidden, ln1, nullptr, xnh, xnl);

    // 2. fused QKV projection (A from planes; weights split in-kernel)
    gemm_hy<0, 1><<<dim3(48, NTOK / TM, 1), 256>>>(
        xnh, xnl, qw, qb, nullptr, NTOK, D_, D_, 0, kw, kb, vw, vb);

    // 3. fused RoPE + Q/K split, V split/transpose
    rope_split_k<<<(NTOK * HN * 64) / 256, 256>>>(pos);
    splitv_k<<<dim3(SQ / 32, HD / 32, BB * HN), dim3(32, 8)>>>();

    // 4. smem-staged mma flash attention (writes hi/lo planes)
    attn_mma_k<<<dim3(SQ / 64, HN, BB), 128>>>();

    // 5. O projection + residual (A = attention planes)
    gemm_hy<0><<<dim3(D_ / TN, NTOK / TM, 1), 256>>>(
        ah, al, ow, hb, hidden, NTOK, D_, D_, 0, nullptr, nullptr, nullptr, nullptr);

    // 6. post-attention RMSNorm (fp32 for routing + planes for GEMMs)
    rmsnorm_sp_k<<<NTOK, 256>>>(hb, ln2, x2, x2h, x2l);

    // 7. routing
    zero_k<<<1, 32>>>();
    route1_k<<<NTOK, 256>>>(x2, gw);
    scan_k<<<1, 1>>>();
    assign_k<<<NTOK / 256, 256>>>();

    // 8. MoE expert GEMMs: fused gate+up (A = x2 planes, gathered), then down (A = inter planes)
    gemm_hy<1, 2><<<dim3(12, 16, EE), 256>>>(
        x2h, x2l, egw, gb, nullptr, 0, DE_, D_, (long)DE_ * D_, euw, ub, nullptr, nullptr);
    swiglu_k<<<(NSLOT * DE_ + 255) / 256, 256>>>();
    gemm_hy<2><<<dim3(D_ / TN, 16, EE), 256>>>(
        ih, il, edw, op, nullptr, 0, D_, DE_, (long)D_ * DE_, nullptr, nullptr, nullptr, nullptr);

    // 9. weighted combine + residual
    final_k<<<NTOK, 256>>>(out);
}

// round 17
// speedup vs baseline: 1.7465x; 1.0106x over previous
#include <cuda_runtime.h>
#include <cuda_bf16.h>
#include <math.h>
#include <stdint.h>

// ---------------- problem constants ----------------
#define BB 2
#define SQ 1024
#define D_ 2048
#define HN 16
#define HD 128
#define NTOK (BB*SQ)       // 2048
#define EE 8
#define DE_ 704
#define NSLOT (NTOK*2)     // 4096 (top-2 per token)

typedef __nv_bfloat16 bf16;

// ---------------- scratch (device globals: no allocations allowed) ----------------
__device__ float g_q   [NTOK*D_];
__device__ float g_k   [NTOK*D_];
__device__ float g_v   [NTOK*D_];
__device__ float g_h   [NTOK*D_];
__device__ float g_xn2 [NTOK*D_];
__device__ float g_gb  [NSLOT*DE_];
__device__ float g_ub  [NSLOT*DE_];
__device__ float g_op  [NSLOT*D_];
__device__ int   g_cnt [EE];
__device__ int   g_cur [EE];
__device__ int   g_off [EE];
__device__ int   g_tope[NTOK*2];
__device__ float g_topw[NTOK*2];
__device__ int   g_slot_tok[NSLOT];
__device__ float g_slot_w  [NSLOT];
__device__ int   g_tok_pos [NTOK*2];
// bf16 hi/lo activation planes (produced for free by producer kernels)
__device__ bf16 g_xnh[NTOK*D_],  g_xnl[NTOK*D_];    // pre-attn norm out
__device__ bf16 g_qh [NTOK*D_],  g_ql [NTOK*D_];
__device__ bf16 g_kh [NTOK*D_],  g_kl [NTOK*D_];
__device__ bf16 g_vth[NTOK*D_],  g_vtl[NTOK*D_];    // V transposed [bh][HD][SQ]
__device__ bf16 g_ah [NTOK*D_],  g_al [NTOK*D_];    // attention out planes
__device__ bf16 g_x2h[NTOK*D_],  g_x2l[NTOK*D_];    // post-attn norm out
__device__ bf16 g_ih [NSLOT*DE_], g_il [NSLOT*DE_]; // swiglu inter planes

// ---------------- helpers ----------------
__device__ __forceinline__ uint32_t smem_u32(const void* p) {
    uint32_t a;
    asm("{ .reg .u64 t; cvta.to.shared.u64 t, %1; cvt.u32.u64 %0, t; }" : "=r"(a) : "l"(p));
    return a;
}
__device__ __forceinline__ void mma_bf16(float* c, const uint32_t* a,
                                         uint32_t b0, uint32_t b1) {
    asm volatile(
        "mma.sync.aligned.m16n8k16.row.col.f32.bf16.bf16.f32 "
        "{%0,%1,%2,%3}, {%4,%5,%6,%7}, {%8,%9}, {%0,%1,%2,%3};"
        : "+f"(c[0]), "+f"(c[1]), "+f"(c[2]), "+f"(c[3])
        : "r"(a[0]), "r"(a[1]), "r"(a[2]), "r"(a[3]), "r"(b0), "r"(b1));
}
__device__ __forceinline__ void ldsm4(uint32_t& r0, uint32_t& r1, uint32_t& r2,
                                      uint32_t& r3, uint32_t addr) {
    asm volatile("ldmatrix.sync.aligned.m8n8.x4.shared.b16 {%0,%1,%2,%3}, [%4];"
                 : "=r"(r0), "=r"(r1), "=r"(r2), "=r"(r3) : "r"(addr));
}
__device__ __forceinline__ void split2(float x0, float x1, uint32_t& wh, uint32_t& wl) {
    bf16 h0 = __float2bfloat16(x0);
    bf16 h1 = __float2bfloat16(x1);
    bf16 l0 = __float2bfloat16(x0 - __bfloat162float(h0));
    bf16 l1 = __float2bfloat16(x1 - __bfloat162float(h1));
    wh = ((uint32_t)__bfloat16_as_ushort(h1) << 16) | __bfloat16_as_ushort(h0);
    wl = ((uint32_t)__bfloat16_as_ushort(l1) << 16) | __bfloat16_as_ushort(l0);
}
__device__ __forceinline__ void split1(float x, bf16& h, bf16& l) {
    h = __float2bfloat16(x);
    l = __float2bfloat16(x - __bfloat162float(h));
}
__device__ __forceinline__ void cpa16(uint32_t dst, const void* src) {
    asm volatile("cp.async.ca.shared.global [%0], [%1], 16;" :: "r"(dst), "l"(src));
}
#define CP_COMMIT() asm volatile("cp.async.commit_group;" ::: "memory")
#define CP_WAIT0()  asm volatile("cp.async.wait_group 0;" ::: "memory")

// ---------------- hybrid tensor GEMM (overlapped mainloop) ----------------
// C[M,N] = A[M,K] * W[N,K]^T (+add).
// A given as bf16 hi/lo planes (AH/AL); W fp32, split in-kernel.
// Mainloop order: barrier FIRST, then STS-next + LDG-next interleaved with
// LDSM/MMA on the current buffer (scoreboard overlap; race-free, see comment).
// MODE 0: dense. MODE 1: A rows gathered via g_slot_tok. MODE 2: A rows contiguous.
// FUSE 1: QKV (blockIdx.x/16 selects W/C). FUSE 2: gate+up (x>=6 -> W2/C2).
#define TM 128
#define TN 128
#define BK 16
#define RS 12   // row stride in 32-bit words (48B) -> conflict-free for ldmatrix

template<int MODE, int FUSE = 0>
__global__ void __launch_bounds__(256) gemm_hy(
    const bf16* __restrict__ AH, const bf16* __restrict__ AL,
    const float* __restrict__ W,
    float* __restrict__ C, const float* __restrict__ addp,
    int M, int Nn, int Kk, long wstride,
    const float* __restrict__ W2, float* __restrict__ C2,
    const float* __restrict__ W3, float* __restrict__ C3)
{
    __shared__ uint32_t AhS[2][TM][RS];
    __shared__ uint32_t AlS[2][TM][RS];
    __shared__ uint32_t BhS[2][TN][RS];
    __shared__ uint32_t BlS[2][TN][RS];

    int e = blockIdx.z;
    int Mloc = M, base = 0;
    int bx = blockIdx.x;
    const float* Wb = W;
    float* Cp = C;
    if (FUSE == 1) {
        int sel = bx >> 4; bx &= 15;
        Wb = (sel == 0) ? W : ((sel == 1) ? W2 : W3);
        Cp = (sel == 0) ? C : ((sel == 1) ? C2 : C3);
    }
    if (FUSE == 2) {
        if (bx >= 6) { bx -= 6; Wb = W2; Cp = C2; }
    }
    const float* Wp = Wb;
    if (MODE != 0) { Mloc = g_cnt[e]; base = g_off[e]; Wp = Wb + (size_t)e * (size_t)wstride; }
    int m0 = blockIdx.y * TM;
    if (m0 >= Mloc) return;
    int n0 = bx * TN;
    int tid = threadIdx.x;

    // ---- A staging: thread -> (row = tid>>1, 16B chunk = tid&1), bf16 planes ----
    int srow = tid >> 1, ch = tid & 1;
    uint32_t aSmemOff = (uint32_t)(srow * 48 + ch * 16);
    int gm = m0 + srow;
    bool av = gm < Mloc;
    int arow;
    if (MODE == 0)      arow = av ? gm : 0;
    else if (MODE == 1) arow = av ? g_slot_tok[base + gm] : 0;
    else                arow = av ? (base + gm) : 0;
    const bf16* pAh = AH + (size_t)arow * Kk + ch * 8;
    const bf16* pAl = AL + (size_t)arow * Kk + ch * 8;

    // ---- B staging: 2 slots per thread, fp32 + in-kernel split ----
    const float* bP[2];
    int rowL[2], c4L[2];
    bool bV[2];
#pragma unroll
    for (int i = 0; i < 2; i++) {
        int v = tid + i * 256;
        int row = v >> 2, c4 = v & 3;
        rowL[i] = row; c4L[i] = c4;
        int gn = n0 + row;
        bV[i] = gn < Nn;
        bP[i] = Wp + (size_t)(bV[i] ? gn : 0) * Kk + c4 * 4;
    }

    int lane = tid & 31, g = lane >> 2, tg = lane & 3;
    int wm = (tid >> 5) & 3;
    int wn = tid >> 7;
    int mbase = wm * 32, nbase = wn * 64;

    uint32_t sAh = smem_u32(AhS), sAl = smem_u32(AlS);
    uint32_t sBh = smem_u32(BhS), sBl = smem_u32(BlS);
    uint32_t aoff[2], boff[4];
#pragma unroll
    for (int mt = 0; mt < 2; mt++)
        aoff[mt] = (uint32_t)((mbase + mt * 16 + (lane & 7) + ((lane >> 3) & 1) * 8) * 48
                              + ((lane >> 4) & 1) * 16);
#pragma unroll
    for (int p = 0; p < 4; p++)
        boff[p] = (uint32_t)((nbase + p * 16 + (lane & 7) + ((lane >> 4) & 1) * 8) * 48
                             + ((lane >> 3) & 1) * 16);

    float acc[2][8][4];
#pragma unroll
    for (int mt = 0; mt < 2; mt++)
#pragma unroll
        for (int nt = 0; nt < 8; nt++)
#pragma unroll
            for (int q = 0; q < 4; q++) acc[mt][nt][q] = 0.f;

    int nk = Kk / BK;
    uint4 rAh, rAl;
    float4 rb[2];
    const uint4 z4 = make_uint4(0, 0, 0, 0);

    // ---- prologue: stage 0 into buf 0 (no sync needed: nobody reads yet) ----
    rAh = av ? *(const uint4*)(pAh) : z4;
    rAl = av ? *(const uint4*)(pAl) : z4;
#pragma unroll
    for (int i = 0; i < 2; i++)
        rb[i] = bV[i] ? *(const float4*)(bP[i]) : make_float4(0,0,0,0);

    *(uint4*)((uint8_t*)AhS + aSmemOff) = rAh;
    *(uint4*)((uint8_t*)AlS + aSmemOff) = rAl;
#pragma unroll
    for (int i = 0; i < 2; i++) {
        int r = rowL[i], w0 = c4L[i] * 2;
        uint32_t h0, l0, h1, l1;
        split2(rb[i].x, rb[i].y, h0, l0);
        split2(rb[i].z, rb[i].w, h1, l1);
        BhS[0][r][w0] = h0; BhS[0][r][w0+1] = h1;
        BlS[0][r][w0] = l0; BlS[0][r][w0+1] = l1;
    }
    // prefetch stage 1 into regs
    if (nk > 1) {
        rAh = av ? *(const uint4*)(pAh + BK) : z4;
        rAl = av ? *(const uint4*)(pAl + BK) : z4;
#pragma unroll
        for (int i = 0; i < 2; i++)
            rb[i] = bV[i] ? *(const float4*)(bP[i] + BK) : make_float4(0,0,0,0);
    }

    int buf = 0;
    for (int it = 0; it < nk; it++) {
        // Barrier first: guarantees (a) buf's stores (made at it-1 / prologue)
        // are visible, and (b) every warp has finished reading buf^1 at it-1,
        // so the stores to buf^1 below cannot race with those reads.
        __syncthreads();

        // ---- overlapped: store next stage to buf^1 + issue LDG for it+2 ----
        if (it + 1 < nk) {
            int nb = buf ^ 1;
            *(uint4*)((uint8_t*)AhS + (size_t)nb * (TM*RS*4) + aSmemOff) = rAh;
            *(uint4*)((uint8_t*)AlS + (size_t)nb * (TM*RS*4) + aSmemOff) = rAl;
#pragma unroll
            for (int i = 0; i < 2; i++) {
                int r = rowL[i], w0 = c4L[i] * 2;
                uint32_t h0, l0, h1, l1;
                split2(rb[i].x, rb[i].y, h0, l0);
                split2(rb[i].z, rb[i].w, h1, l1);
                BhS[nb][r][w0] = h0; BhS[nb][r][w0+1] = h1;
                BlS[nb][r][w0] = l0; BlS[nb][r][w0+1] = l1;
            }
            if (it + 2 < nk) {
                int k0 = (it + 2) * BK;
                rAh = av ? *(const uint4*)(pAh + k0) : z4;
                rAl = av ? *(const uint4*)(pAl + k0) : z4;
#pragma unroll
                for (int i = 0; i < 2; i++)
                    rb[i] = bV[i] ? *(const float4*)(bP[i] + k0) : make_float4(0,0,0,0);
            }
        }

        // ---- compute from buf (interleaves with the stores above) ----
        uint32_t bufo = (uint32_t)buf * (TM * RS * 4);
        uint32_t ah[2][4], al[2][4];
#pragma unroll
        for (int mt = 0; mt < 2; mt++) {
            ldsm4(ah[mt][0], ah[mt][1], ah[mt][2], ah[mt][3], sAh + bufo + aoff[mt]);
            ldsm4(al[mt][0], al[mt][1], al[mt][2], al[mt][3], sAl + bufo + aoff[mt]);
        }
#pragma unroll
        for (int p = 0; p < 4; p++) {
            uint32_t b00, b01, b10, b11, c00, c01, c10, c11;
            ldsm4(b00, b01, b10, b11, sBh + bufo + boff[p]);
            ldsm4(c00, c01, c10, c11, sBl + bufo + boff[p]);
#pragma unroll
            for (int mt = 0; mt < 2; mt++) {
                mma_bf16(acc[mt][2*p],   ah[mt], b00, b01);
                mma_bf16(acc[mt][2*p],   ah[mt], c00, c01);
                mma_bf16(acc[mt][2*p],   al[mt], b00, b01);
                mma_bf16(acc[mt][2*p+1], ah[mt], b10, b11);
                mma_bf16(acc[mt][2*p+1], ah[mt], c10, c11);
                mma_bf16(acc[mt][2*p+1], al[mt], b10, b11);
            }
        }
        buf ^= 1;
    }

    // ---- epilogue: c0/c1 -> (row g, cols 2tg,2tg+1), c2/c3 -> row g+8 ----
#pragma unroll
    for (int mt = 0; mt < 2; mt++) {
#pragma unroll
        for (int nt = 0; nt < 8; nt++) {
            int gc = n0 + nbase + nt * 8 + tg * 2;
            if (gc >= Nn) continue;
            int gm0 = m0 + mbase + mt * 16 + g;
#pragma unroll
            for (int hrow = 0; hrow < 2; hrow++) {
                int gmr = gm0 + hrow * 8;
                if (gmr >= Mloc) continue;
                int crow = (MODE == 0) ? gmr : (base + gmr);
                size_t off = (size_t)crow * Nn + gc;
                float2 vv = make_float2(acc[mt][nt][hrow * 2], acc[mt][nt][hrow * 2 + 1]);
                if (MODE == 0 && addp) {
                    float2 rv = *(const float2*)(addp + off);
                    vv.x += rv.x; vv.y += rv.y;
                }
                *(float2*)(Cp + off) = vv;
            }
        }
    }
}

// ---------------- RMSNorm with split output ----------------
__global__ void rmsnorm_sp_k(const float* __restrict__ x, const float* __restrict__ w,
                             float* __restrict__ o, bf16* __restrict__ oh,
                             bf16* __restrict__ ol) {
    int n = blockIdx.x;
    const float* xr = x + (size_t)n * D_;
    float s = 0.f;
    for (int d = threadIdx.x; d < D_; d += 256) { float v = xr[d]; s += v * v; }
    __shared__ float red[256];
    red[threadIdx.x] = s; __syncthreads();
    for (int st = 128; st > 0; st >>= 1) {
        if (threadIdx.x < st) red[threadIdx.x] += red[threadIdx.x + st];
        __syncthreads();
    }
    float inv = rsqrtf(red[0] / (float)D_ + 1e-6f);
    size_t ro = (size_t)n * D_;
    for (int d = threadIdx.x; d < D_; d += 256) {
        float v = xr[d] * inv * w[d];
        if (o) o[ro + d] = v;
        bf16 h, l;
        split1(v, h, l);
        oh[ro + d] = h; ol[ro + d] = l;
    }
}

// ---------------- fused RoPE + bf16 hi/lo split for Q,K ----------------
__global__ void rope_split_k(const int* __restrict__ pos) {
    int idx = blockIdx.x * 256 + threadIdx.x;
    if (idx >= NTOK * HN * 64) return;
    int j  = idx & 63;
    int hh = (idx >> 6) & 15;
    int t  = idx >> 10;
    float p = (float)pos[t];
    float inv = expf(-((float)(2 * j) / 128.0f) * 9.210340371976184f);
    float fr = p * inv;
    float sn, cs;
    sincosf(fr, &sn, &cs);
    size_t base = (size_t)t * D_ + hh * HD + j;
    bf16 h, l;
    float x1 = g_q[base], x2 = g_q[base + 64];
    float r1 = x1 * cs - x2 * sn, r2 = x2 * cs + x1 * sn;
    split1(r1, h, l); g_qh[base] = h;      g_ql[base] = l;
    split1(r2, h, l); g_qh[base + 64] = h; g_ql[base + 64] = l;
    x1 = g_k[base]; x2 = g_k[base + 64];
    r1 = x1 * cs - x2 * sn; r2 = x2 * cs + x1 * sn;
    split1(r1, h, l); g_kh[base] = h;      g_kl[base] = l;
    split1(r2, h, l); g_kh[base + 64] = h; g_kl[base + 64] = l;
}

// ---------------- split V + transpose to [bh][dim][seq] bf16 hi/lo ----------------
__global__ void splitv_k() {
    __shared__ bf16 sh[32][33], sl[32][33];
    int tx = threadIdx.x, ty = threadIdx.y;      // (32, 8)
    int s0 = blockIdx.x * 32;
    int d0 = blockIdx.y * 32;
    int bh = blockIdx.z;
    int b = bh >> 4, hh = bh & 15;
#pragma unroll
    for (int i = 0; i < 4; i++) {
        int sr = ty + i * 8;
        float v = g_v[((size_t)(b * SQ + s0 + sr)) * D_ + hh * HD + d0 + tx];
        bf16 h, l;
        split1(v, h, l);
        sh[sr][tx] = h; sl[sr][tx] = l;
    }
    __syncthreads();
#pragma unroll
    for (int i = 0; i < 4; i++) {
        int dr = ty + i * 8;
        size_t o = ((size_t)bh * HD + d0 + dr) * SQ + s0 + tx;
        g_vth[o] = sh[tx][dr];
        g_vtl[o] = sl[tx][dr];
    }
}

// ---------------- flash attention: smem-staged K/V + mma.sync bf16x3 ----------------
// grid (SQ/64, HN, BB), block 128. Epilogue writes bf16 hi/lo planes for O-proj.
__global__ void __launch_bounds__(128) attn_mma_k()
{
    __shared__ __align__(16) uint8_t sm[49152];
    uint32_t sb = smem_u32(sm);
    int tid = threadIdx.x;
    int w = tid >> 5, lane = tid & 31;
    int g = lane >> 2, tg = lane & 3;
    int hh = blockIdx.y, b = blockIdx.z;
    int qsb = blockIdx.x * 64;
    int qs0 = qsb + w * 16;
    int bh = b * HN + hh;

    uint32_t qfh[8][4], qfl[8][4];
    size_t qr0 = ((size_t)(b * SQ + qs0 + g)) * D_ + hh * HD;
    size_t qr1 = qr0 + (size_t)8 * D_;
#pragma unroll
    for (int ks = 0; ks < 8; ks++) {
        int c0 = ks * 16 + 2 * tg;
        qfh[ks][0] = *(const uint32_t*)&g_qh[qr0 + c0];
        qfh[ks][1] = *(const uint32_t*)&g_qh[qr1 + c0];
        qfh[ks][2] = *(const uint32_t*)&g_qh[qr0 + c0 + 8];
        qfh[ks][3] = *(const uint32_t*)&g_qh[qr1 + c0 + 8];
        qfl[ks][0] = *(const uint32_t*)&g_ql[qr0 + c0];
        qfl[ks][1] = *(const uint32_t*)&g_ql[qr1 + c0];
        qfl[ks][2] = *(const uint32_t*)&g_ql[qr0 + c0 + 8];
        qfl[ks][3] = *(const uint32_t*)&g_ql[qr1 + c0 + 8];
    }

    uint32_t lm_row = (lane & 7) + ((lane >> 4) & 1) * 8;
    uint32_t lm_col = ((lane >> 3) & 1) * 16;

    float m0 = -1e30f, m1 = -1e30f, l0 = 0.f, l1 = 0.f;
    float Oa[16][4];
#pragma unroll
    for (int nt = 0; nt < 16; nt++)
#pragma unroll
        for (int q = 0; q < 4; q++) Oa[nt][q] = 0.f;

    const float SC = 0.08838834764831845f;
    int row0 = qs0 + g, row1 = row0 + 8;
    int nsteps = qsb / 32 + 2;

    for (int step = 0; step < nsteps; step++) {
        int kt = step * 32;
        {
            size_t kg = ((size_t)(b * SQ + kt)) * D_ + hh * HD;
#pragma unroll
            for (int i = 0; i < 4; i++) {
                int idx = tid * 4 + i;
                int tok = idx >> 4, ks = (idx >> 1) & 7, c = idx & 1;
                size_t so = kg + (size_t)tok * D_ + ks * 16 + c * 8;
                uint32_t dst = sb + (uint32_t)(ks * 1536 + tok * 48 + c * 16);
                cpa16(dst,         g_kh + so);
                cpa16(dst + 12288, g_kl + so);
            }
            size_t vg = (size_t)bh * HD * SQ + kt;
#pragma unroll
            for (int i = 0; i < 4; i++) {
                int idx = tid * 4 + i;
                int dim = idx >> 2, ks2 = (idx >> 1) & 1, c = idx & 1;
                size_t so = vg + (size_t)dim * SQ + ks2 * 16 + c * 8;
                uint32_t dst = sb + 24576u + (uint32_t)(ks2 * 6144 + dim * 48 + c * 16);
                cpa16(dst,         g_vth + so);
                cpa16(dst + 12288, g_vtl + so);
            }
        }
        CP_COMMIT();
        CP_WAIT0();
        __syncthreads();

        float s[4][4];
#pragma unroll
        for (int nt = 0; nt < 4; nt++)
#pragma unroll
            for (int q = 0; q < 4; q++) s[nt][q] = 0.f;

#pragma unroll
        for (int ks = 0; ks < 8; ks++) {
#pragma unroll
            for (int p = 0; p < 2; p++) {
                uint32_t ka = sb + (uint32_t)(ks * 1536 + (p * 16 + lm_row) * 48) + lm_col;
                uint32_t b00, b01, b10, b11, c00, c01, c10, c11;
                ldsm4(b00, b01, b10, b11, ka);
                ldsm4(c00, c01, c10, c11, ka + 12288);
                mma_bf16(s[2*p],   qfh[ks], b00, b01);
                mma_bf16(s[2*p],   qfh[ks], c00, c01);
                mma_bf16(s[2*p],   qfl[ks], b00, b01);
                mma_bf16(s[2*p+1], qfh[ks], b10, b11);
                mma_bf16(s[2*p+1], qfh[ks], c10, c11);
                mma_bf16(s[2*p+1], qfl[ks], b10, b11);
            }
        }

#pragma unroll
        for (int nt = 0; nt < 4; nt++) {
            int col = kt + nt * 8 + 2 * tg;
            s[nt][0] = (col     <= row0) ? s[nt][0] * SC : -1e30f;
            s[nt][1] = (col + 1 <= row0) ? s[nt][1] * SC : -1e30f;
            s[nt][2] = (col     <= row1) ? s[nt][2] * SC : -1e30f;
            s[nt][3] = (col + 1 <= row1) ? s[nt][3] * SC : -1e30f;
        }

        float mx0 = -1e30f, mx1 = -1e30f;
#pragma unroll
        for (int nt = 0; nt < 4; nt++) {
            mx0 = fmaxf(mx0, fmaxf(s[nt][0], s[nt][1]));
            mx1 = fmaxf(mx1, fmaxf(s[nt][2], s[nt][3]));
        }
        mx0 = fmaxf(mx0, __shfl_xor_sync(0xffffffff, mx0, 1));
        mx0 = fmaxf(mx0, __shfl_xor_sync(0xffffffff, mx0, 2));
        mx1 = fmaxf(mx1, __shfl_xor_sync(0xffffffff, mx1, 1));
        mx1 = fmaxf(mx1, __shfl_xor_sync(0xffffffff, mx1, 2));
        float mn0 = fmaxf(m0, mx0), mn1 = fmaxf(m1, mx1);
        float a0 = __expf(m0 - mn0), a1 = __expf(m1 - mn1);
        float sum0 = 0.f, sum1 = 0.f;
#pragma unroll
        for (int nt = 0; nt < 4; nt++) {
            s[nt][0] = __expf(s[nt][0] - mn0);
            s[nt][1] = __expf(s[nt][1] - mn0);
            s[nt][2] = __expf(s[nt][2] - mn1);
            s[nt][3] = __expf(s[nt][3] - mn1);
            sum0 += s[nt][0] + s[nt][1];
            sum1 += s[nt][2] + s[nt][3];
        }
        sum0 += __shfl_xor_sync(0xffffffff, sum0, 1);
        sum0 += __shfl_xor_sync(0xffffffff, sum0, 2);
        sum1 += __shfl_xor_sync(0xffffffff, sum1, 1);
        sum1 += __shfl_xor_sync(0xffffffff, sum1, 2);
        l0 = l0 * a0 + sum0; l1 = l1 * a1 + sum1;
        m0 = mn0; m1 = mn1;

#pragma unroll
        for (int nt = 0; nt < 16; nt++) {
            Oa[nt][0] *= a0; Oa[nt][1] *= a0;
            Oa[nt][2] *= a1; Oa[nt][3] *= a1;
        }

        uint32_t pah[2][4], pal[2][4];
#pragma unroll
        for (int ks2 = 0; ks2 < 2; ks2++) {
            int na = ks2 * 2, nb = na + 1;
            split2(s[na][0], s[na][1], pah[ks2][0], pal[ks2][0]);
            split2(s[na][2], s[na][3], pah[ks2][1], pal[ks2][1]);
            split2(s[nb][0], s[nb][1], pah[ks2][2], pal[ks2][2]);
            split2(s[nb][2], s[nb][3], pah[ks2][3], pal[ks2][3]);
        }

#pragma unroll
        for (int ks2 = 0; ks2 < 2; ks2++) {
#pragma unroll
            for (int p = 0; p < 8; p++) {
                uint32_t va = sb + 24576u
                            + (uint32_t)(ks2 * 6144 + (p * 16 + lm_row) * 48) + lm_col;
                uint32_t v00, v01, v10, v11, u00, u01, u10, u11;
                ldsm4(v00, v01, v10, v11, va);
                ldsm4(u00, u01, u10, u11, va + 12288);
                mma_bf16(Oa[2*p],   pah[ks2], v00, v01);
                mma_bf16(Oa[2*p],   pah[ks2], u00, u01);
                mma_bf16(Oa[2*p],   pal[ks2], v00, v01);
                mma_bf16(Oa[2*p+1], pah[ks2], v10, v11);
                mma_bf16(Oa[2*p+1], pah[ks2], u10, u11);
                mma_bf16(Oa[2*p+1], pal[ks2], v10, v11);
            }
        }
        __syncthreads();
    }

    // epilogue: write bf16 hi/lo planes for the O-projection GEMM
    float i0 = 1.f / l0, i1 = 1.f / l1;
    size_t or0 = ((size_t)(b * SQ + qs0 + g)) * D_ + hh * HD;
    size_t or1 = or0 + (size_t)8 * D_;
#pragma unroll
    for (int nt = 0; nt < 16; nt++) {
        int col = nt * 8 + 2 * tg;
        uint32_t h, l;
        split2(Oa[nt][0] * i0, Oa[nt][1] * i0, h, l);
        *(uint32_t*)&g_ah[or0 + col] = h;
        *(uint32_t*)&g_al[or0 + col] = l;
        split2(Oa[nt][2] * i1, Oa[nt][3] * i1, h, l);
        *(uint32_t*)&g_ah[or1 + col] = h;
        *(uint32_t*)&g_al[or1 + col] = l;
    }
}

// ---------------- MoE routing ----------------
__global__ void zero_k() {
    if (threadIdx.x < EE) { g_cnt[threadIdx.x] = 0; g_cur[threadIdx.x] = 0; }
}

__global__ void route1_k(const float* __restrict__ x, const float* __restrict__ gw) {
    int n = blockIdx.x;
    float part[EE];
#pragma unroll
    for (int e = 0; e < EE; e++) part[e] = 0.f;
    for (int d = threadIdx.x; d < D_; d += 256) {
        float xv = x[(size_t)n * D_ + d];
#pragma unroll
        for (int e = 0; e < EE; e++) part[e] = fmaf(xv, gw[e * D_ + d], part[e]);
    }
    __shared__ float red[256];
    __shared__ float lg[EE];
    for (int e = 0; e < EE; e++) {
        red[threadIdx.x] = part[e]; __syncthreads();
        for (int st = 128; st > 0; st >>= 1) {
            if (threadIdx.x < st) red[threadIdx.x] += red[threadIdx.x + st];
            __syncthreads();
        }
        if (threadIdx.x == 0) lg[e] = red[0];
        __syncthreads();
    }
    if (threadIdx.x == 0) {
        int i0 = 0; float b0 = lg[0];
        for (int e = 1; e < EE; e++) if (lg[e] > b0) { b0 = lg[e]; i0 = e; }
        int i1 = -1; float b1 = -1e30f;
        for (int e = 0; e < EE; e++) { if (e == i0) continue; if (lg[e] > b1) { b1 = lg[e]; i1 = e; } }
        float m = fmaxf(b0, b1);
        float w0 = __expf(b0 - m), w1 = __expf(b1 - m);
        float s = w0 + w1; w0 /= s; w1 /= s;
        g_tope[n*2] = i0; g_tope[n*2+1] = i1;
        g_topw[n*2] = w0; g_topw[n*2+1] = w1;
        atomicAdd(&g_cnt[i0], 1); atomicAdd(&g_cnt[i1], 1);
    }
}

__global__ void scan_k() {
    int o = 0;
    for (int e = 0; e < EE; e++) { g_off[e] = o; o += g_cnt[e]; }
}

__global__ void assign_k() {
    int n = blockIdx.x * 256 + threadIdx.x;
    if (n >= NTOK) return;
#pragma unroll
    for (int kk = 0; kk < 2; kk++) {
        int e = g_tope[n*2 + kk];
        int p = g_off[e] + atomicAdd(&g_cur[e], 1);
        g_slot_tok[p] = n;
        g_slot_w[p]   = g_topw[n*2 + kk];
        g_tok_pos[n*2 + kk] = p;
    }
}

// ---------------- swiglu with split (plane) output ----------------
__global__ void swiglu_k() {
    int i = blockIdx.x * 256 + threadIdx.x;
    if (i >= NSLOT * DE_) return;
    float g = g_gb[i], u = g_ub[i];
    float sig = 1.f / (1.f + __expf(-g));
    float v = g * sig * u;
    bf16 h, l;
    split1(v, h, l);
    g_ih[i] = h; g_il[i] = l;
}

__global__ void final_k(float* __restrict__ out) {
    int n = blockIdx.x;
    int p0 = g_tok_pos[n*2], p1 = g_tok_pos[n*2 + 1];
    float w0 = g_slot_w[p0], w1 = g_slot_w[p1];
    size_t hb = (size_t)n * D_;
    for (int d = threadIdx.x * 4; d < D_; d += 1024) {
        float4 hv = *(const float4*)(g_h + hb + d);
        float4 a  = *(const float4*)(g_op + (size_t)p0 * D_ + d);
        float4 b4 = *(const float4*)(g_op + (size_t)p1 * D_ + d);
        float4 o;
        o.x = hv.x + w0 * a.x + w1 * b4.x;
        o.y = hv.y + w0 * a.y + w1 * b4.y;
        o.z = hv.z + w0 * a.z + w1 * b4.z;
        o.w = hv.w + w0 * a.w + w1 * b4.w;
        *(float4*)(out + hb + d) = o;
    }
}

// ---------------- launcher ----------------
extern "C" void kernel_launch(void* const* d_in, const int* in_sizes, int n_in,
                              void* d_out, int out_size) {
    const float* hidden = (const float*)d_in[0];
    const float* ln1    = (const float*)d_in[1];
    const float* ln2    = (const float*)d_in[2];
    const float* qw     = (const float*)d_in[3];
    const float* kw     = (const float*)d_in[4];
    const float* vw     = (const float*)d_in[5];
    const float* ow     = (const float*)d_in[6];
    const float* gw     = (const float*)d_in[7];
    const float* egw    = (const float*)d_in[8];
    const float* euw    = (const float*)d_in[9];
    const float* edw    = (const float*)d_in[10];
    const int*   pos    = (const int*)d_in[11];
    float* out = (float*)d_out;

    float *qb, *kb, *vb, *hb, *x2, *gb, *ub, *op;
    cudaGetSymbolAddress((void**)&qb, g_q);
    cudaGetSymbolAddress((void**)&kb, g_k);
    cudaGetSymbolAddress((void**)&vb, g_v);
    cudaGetSymbolAddress((void**)&hb, g_h);
    cudaGetSymbolAddress((void**)&x2, g_xn2);
    cudaGetSymbolAddress((void**)&gb, g_gb);
    cudaGetSymbolAddress((void**)&ub, g_ub);
    cudaGetSymbolAddress((void**)&op, g_op);

    bf16 *xnh, *xnl, *ah, *al, *x2h, *x2l, *ih, *il;
    cudaGetSymbolAddress((void**)&xnh, g_xnh); cudaGetSymbolAddress((void**)&xnl, g_xnl);
    cudaGetSymbolAddress((void**)&ah,  g_ah);  cudaGetSymbolAddress((void**)&al,  g_al);
    cudaGetSymbolAddress((void**)&x2h, g_x2h); cudaGetSymbolAddress((void**)&x2l, g_x2l);
    cudaGetSymbolAddress((void**)&ih,  g_ih);  cudaGetSymbolAddress((void**)&il,  g_il);

    // 1. pre-attention RMSNorm (emit bf16 hi/lo planes only)
    rmsnorm_sp_k<<<NTOK, 256>>>(hidden, ln1, nullptr, xnh, xnl);

    // 2. fused QKV projection (A from planes; weights split in-kernel)
    gemm_hy<0, 1><<<dim3(48, NTOK / TM, 1), 256>>>(
        xnh, xnl, qw, qb, nullptr, NTOK, D_, D_, 0, kw, kb, vw, vb);

    // 3. fused RoPE + Q/K split, V split/transpose
    rope_split_k<<<(NTOK * HN * 64) / 256, 256>>>(pos);
    splitv_k<<<dim3(SQ / 32, HD / 32, BB * HN), dim3(32, 8)>>>();

    // 4. smem-staged mma flash attention (writes hi/lo planes)
    attn_mma_k<<<dim3(SQ / 64, HN, BB), 128>>>();

    // 5. O projection + residual (A = attention planes)
    gemm_hy<0><<<dim3(D_ / TN, NTOK / TM, 1), 256>>>(
        ah, al, ow, hb, hidden, NTOK, D_, D_, 0, nullptr, nullptr, nullptr, nullptr);

    // 6. post-attention RMSNorm (fp32 for routing + planes for GEMMs)
    rmsnorm_sp_k<<<NTOK, 256>>>(hb, ln2, x2, x2h, x2l);

    // 7. routing
    zero_k<<<1, 32>>>();
    route1_k<<<NTOK, 256>>>(x2, gw);
    scan_k<<<1, 1>>>();
    assign_k<<<NTOK / 256, 256>>>();

    // 8. MoE expert GEMMs: fused gate+up (A = x2 planes, gathered), then down (A = inter planes)
    gemm_hy<1, 2><<<dim3(12, 16, EE), 256>>>(
        x2h, x2l, egw, gb, nullptr, 0, DE_, D_, (long)DE_ * D_, euw, ub, nullptr, nullptr);
    swiglu_k<<<(NSLOT * DE_ + 255) / 256, 256>>>();
    gemm_hy<2><<<dim3(D_ / TN, 16, EE), 256>>>(
        ih, il, edw, op, nullptr, 0, D_, DE_, (long)D_ * DE_, nullptr, nullptr, nullptr, nullptr);

    // 9. weighted combine + residual
    final_k<<<NTOK, 256>>>(out);
}